// round 12
// baseline (speedup 1.0000x reference)
#include <cuda_runtime.h>
#include <cuda_fp16.h>
#include <cstdint>

#define BB   4
#define HH   16
#define SS   2048
#define HD   64
#define DIN  1024
#define DOUT 1024
#define INV256 0.00390625f

// ---------------------------------------------------------------------------
// Scratch (__device__ globals; no allocations allowed)
// All "lo" limbs are stored pre-scaled by 256 (kept normal in fp16).
// ---------------------------------------------------------------------------
__device__ __half g_xh[BB * SS * DIN];
__device__ __half g_xl[BB * SS * DIN];
__device__ __half g_wth[4 * DIN * DOUT];     // W^T [n][k]
__device__ __half g_wtl[4 * DIN * DOUT];
__device__ __half g_qh[BB * HH * SS * HD];   // Q (pre-scaled) [B,H,S,HD]
__device__ __half g_ql[BB * HH * SS * HD];
__device__ __half g_kh[BB * HH * SS * HD];
__device__ __half g_kl[BB * HH * SS * HD];
__device__ __half g_vh[BB * HH * SS * HD];
__device__ __half g_vl[BB * HH * SS * HD];
__device__ __half g_cxh[BB * SS * DOUT];     // ctx [8192][1024]
__device__ __half g_cxl[BB * SS * DOUT];

// ---------------------------------------------------------------------------
// Helpers
// ---------------------------------------------------------------------------
__device__ __forceinline__ uint32_t smem_u32(const void* p) {
    uint32_t a;
    asm("{ .reg .u64 t; cvta.to.shared.u64 t, %1; cvt.u32.u64 %0, t; }" : "=r"(a) : "l"(p));
    return a;
}
__device__ __forceinline__ uint32_t packh2(float a, float b) {
    __half2 t = __floats2half2_rn(a, b);
    return *(uint32_t*)&t;
}
__device__ __forceinline__ uint32_t packh2h(__half a, __half b) {
    __half2 t = __halves2half2(a, b);
    return *(uint32_t*)&t;
}
__device__ __forceinline__ float2 uph2(uint32_t r) {
    return __half22float2(*(__half2*)&r);
}
__device__ __forceinline__ void ldsm4(uint32_t& r0, uint32_t& r1, uint32_t& r2, uint32_t& r3,
                                      uint32_t addr) {
    asm volatile("ldmatrix.sync.aligned.m8n8.x4.shared.b16 {%0,%1,%2,%3}, [%4];"
                 : "=r"(r0), "=r"(r1), "=r"(r2), "=r"(r3) : "r"(addr));
}
__device__ __forceinline__ void ldsm4t(uint32_t& r0, uint32_t& r1, uint32_t& r2, uint32_t& r3,
                                       uint32_t addr) {
    asm volatile("ldmatrix.sync.aligned.m8n8.x4.trans.shared.b16 {%0,%1,%2,%3}, [%4];"
                 : "=r"(r0), "=r"(r1), "=r"(r2), "=r"(r3) : "r"(addr));
}
// fp16 inputs, f32 accumulator (main term)
__device__ __forceinline__ void mma_f32(float* c, const uint32_t* a, const uint32_t* b) {
    asm volatile(
        "mma.sync.aligned.m16n8k16.row.col.f32.f16.f16.f32 "
        "{%0,%1,%2,%3}, {%4,%5,%6,%7}, {%8,%9}, {%0,%1,%2,%3};"
        : "+f"(c[0]), "+f"(c[1]), "+f"(c[2]), "+f"(c[3])
        : "r"(a[0]), "r"(a[1]), "r"(a[2]), "r"(a[3]), "r"(b[0]), "r"(b[1]));
}
// fp16 inputs, f16 accumulator (cross terms; carries only ~2^-11 of signal)
__device__ __forceinline__ void mma_f16(uint32_t* c, const uint32_t* a, const uint32_t* b) {
    asm volatile(
        "mma.sync.aligned.m16n8k16.row.col.f16.f16.f16.f16 "
        "{%0,%1}, {%2,%3,%4,%5}, {%6,%7}, {%0,%1};"
        : "+r"(c[0]), "+r"(c[1])
        : "r"(a[0]), "r"(a[1]), "r"(a[2]), "r"(a[3]), "r"(b[0]), "r"(b[1]));
}
__device__ __forceinline__ void cp16(uint32_t dst, const void* src) {
    asm volatile("cp.async.cg.shared.global [%0], [%1], 16;" :: "r"(dst), "l"(src));
}
__device__ __forceinline__ void cp_commit() { asm volatile("cp.async.commit_group;" ::: "memory"); }
__device__ __forceinline__ void cp_wait1()  { asm volatile("cp.async.wait_group 1;" ::: "memory"); }
__device__ __forceinline__ void cp_wait0()  { asm volatile("cp.async.wait_group 0;" ::: "memory"); }

// ---------------------------------------------------------------------------
// Conversion kernels (fp32 -> fp16 hi + fp16 lo*256)
// ---------------------------------------------------------------------------
__global__ __launch_bounds__(256) void conv_x_kernel(const float* __restrict__ x)
{
    int i = (blockIdx.x * 256 + threadIdx.x) * 4;
    float4 v = *(const float4*)(x + i);
    __half h0 = __float2half_rn(v.x), h1 = __float2half_rn(v.y);
    __half h2 = __float2half_rn(v.z), h3 = __float2half_rn(v.w);
    float l0 = (v.x - __half2float(h0)) * 256.f, l1 = (v.y - __half2float(h1)) * 256.f;
    float l2 = (v.z - __half2float(h2)) * 256.f, l3 = (v.w - __half2float(h3)) * 256.f;
    *(uint2*)&g_xh[i] = make_uint2(packh2h(h0, h1), packh2h(h2, h3));
    *(uint2*)&g_xl[i] = make_uint2(packh2(l0, l1), packh2(l2, l3));
}

__global__ __launch_bounds__(256) void conv_w_kernel(
    const float* __restrict__ Wq, const float* __restrict__ Wk,
    const float* __restrict__ Wv, const float* __restrict__ Wo)
{
    const int z = blockIdx.z;
    const float* W = (z == 0) ? Wq : (z == 1) ? Wk : (z == 2) ? Wv : Wo;
    __shared__ float t[32][33];
    const int k0 = blockIdx.y * 32, n0 = blockIdx.x * 32;
    const int tx = threadIdx.x, ty = threadIdx.y;   // 32 x 8
    #pragma unroll
    for (int i = 0; i < 4; ++i)
        t[ty + i * 8][tx] = W[(size_t)(k0 + ty + i * 8) * DOUT + n0 + tx];
    __syncthreads();
    __half* wh = g_wth + (size_t)z * DIN * DOUT;
    __half* wl = g_wtl + (size_t)z * DIN * DOUT;
    #pragma unroll
    for (int i = 0; i < 4; ++i) {
        int n = n0 + ty + i * 8, k = k0 + tx;
        float v = t[tx][ty + i * 8];                 // = W[k][n]
        __half h = __float2half_rn(v);
        wh[(size_t)n * DIN + k] = h;
        wl[(size_t)n * DIN + k] = __float2half_rn((v - __half2float(h)) * 256.f);
    }
}

// ---------------------------------------------------------------------------
// fp16 hi/lo split GEMM.  CTA 64x128, 128 threads (warp 32x64), KC=32,
// 2 stages, 3 CTAs/SM.  Main pass f32-acc; cross passes f16-acc, merged /256
// per chunk.
// ---------------------------------------------------------------------------
#define KC     32
#define PITCH  80
#define ATILE  (64 * PITCH)
#define BTILE  (128 * PITCH)
#define STAGEB (2 * ATILE + 2 * BTILE)   // 30720
#define GSMEM  (2 * STAGEB)              // 61440 -> 3 CTAs/SM

template<int MODE>
__global__ __launch_bounds__(128, 3) void mma_gemm(const float* __restrict__ bias,
                                                   float* __restrict__ dout)
{
    extern __shared__ char smc[];
    const uint32_t smb = smem_u32(smc);

    const int tid  = threadIdx.x;
    const int lane = tid & 31;
    const int wid  = tid >> 5;
    const int wm   = (wid & 1) * 32;
    const int wn   = (wid >> 1) * 64;

    const int m0 = blockIdx.x * 64;
    const int n0 = blockIdx.y * 128;
    const int bz = (MODE == 0) ? blockIdx.z : 3;

    const __half* Ah = (MODE == 0) ? g_xh : g_cxh;
    const __half* Al = (MODE == 0) ? g_xl : g_cxl;
    const __half* Bh = g_wth + (size_t)bz * DIN * DOUT;
    const __half* Bl = g_wtl + (size_t)bz * DIN * DOUT;

    const char* agh = (const char*)Ah + ((size_t)m0 * DIN) * 2;
    const char* agl = (const char*)Al + ((size_t)m0 * DIN) * 2;
    const char* bgh = (const char*)Bh + ((size_t)n0 * DIN) * 2;
    const char* bgl = (const char*)Bl + ((size_t)n0 * DIN) * 2;

    auto load = [&](int c, int st) {
        const uint32_t base = smb + st * STAGEB;
        const size_t cko = (size_t)c * KC * 2;
        #pragma unroll
        for (int i = 0; i < 2; ++i) {
            int s   = tid + i * 128;
            int r   = s >> 2;
            int seg = s & 3;
            size_t  go  = (size_t)r * (DIN * 2) + cko + seg * 16;
            uint32_t dof = r * PITCH + seg * 16;
            cp16(base + dof,         agh + go);
            cp16(base + ATILE + dof, agl + go);
        }
        #pragma unroll
        for (int i = 0; i < 4; ++i) {
            int s   = tid + i * 128;
            int r   = s >> 2;
            int seg = s & 3;
            size_t  go  = (size_t)r * (DIN * 2) + cko + seg * 16;
            uint32_t dof = r * PITCH + seg * 16;
            cp16(base + 2 * ATILE + dof,         bgh + go);
            cp16(base + 2 * ATILE + BTILE + dof, bgl + go);
        }
    };

    float C1[2][8][4] = {};

    const uint32_t aRow = wm + (lane & 15);
    const uint32_t aCol = (lane >> 4) * 16;
    const uint32_t bRow = wn + ((lane >> 4) << 3) + (lane & 7);
    const uint32_t bCol = ((lane >> 3) & 1) * 16;

    load(0, 0);
    cp_commit();

    for (int c = 0; c < DIN / KC; ++c) {
        const int st = c & 1;
        if (c + 1 < DIN / KC) { load(c + 1, st ^ 1); cp_commit(); cp_wait1(); }
        else                  { cp_wait0(); }
        __syncthreads();

        const uint32_t sA = smb + st * STAGEB;
        const uint32_t sB = sA + 2 * ATILE;

        uint32_t C2[2][8][2];
        #pragma unroll
        for (int i = 0; i < 2; ++i)
            #pragma unroll
            for (int j = 0; j < 8; ++j) { C2[i][j][0] = 0u; C2[i][j][1] = 0u; }

        #pragma unroll
        for (int ks = 0; ks < 2; ++ks) {
            uint32_t ah[2][4], al[2][4], bh[8][2], bl[8][2];
            #pragma unroll
            for (int i = 0; i < 2; ++i) {
                uint32_t ad = sA + (aRow + i * 16) * PITCH + ks * 32 + aCol;
                ldsm4(ah[i][0], ah[i][1], ah[i][2], ah[i][3], ad);
                ldsm4(al[i][0], al[i][1], al[i][2], al[i][3], ad + ATILE);
            }
            #pragma unroll
            for (int p = 0; p < 4; ++p) {
                uint32_t bd = sB + (bRow + p * 16) * PITCH + ks * 32 + bCol;
                ldsm4(bh[2*p][0], bh[2*p][1], bh[2*p+1][0], bh[2*p+1][1], bd);
                ldsm4(bl[2*p][0], bl[2*p][1], bl[2*p+1][0], bl[2*p+1][1], bd + BTILE);
            }
            #pragma unroll
            for (int i = 0; i < 2; ++i)
                #pragma unroll
                for (int j = 0; j < 8; ++j)
                    mma_f32(C1[i][j], ah[i], bh[j]);
            #pragma unroll
            for (int i = 0; i < 2; ++i)
                #pragma unroll
                for (int j = 0; j < 8; ++j)
                    mma_f16(C2[i][j], ah[i], bl[j]);
            #pragma unroll
            for (int i = 0; i < 2; ++i)
                #pragma unroll
                for (int j = 0; j < 8; ++j)
                    mma_f16(C2[i][j], al[i], bh[j]);
        }
        // merge cross terms (scaled x256) into f32 accumulators
        #pragma unroll
        for (int i = 0; i < 2; ++i)
            #pragma unroll
            for (int j = 0; j < 8; ++j) {
                float2 p0 = uph2(C2[i][j][0]);
                float2 p1 = uph2(C2[i][j][1]);
                C1[i][j][0] = fmaf(p0.x, INV256, C1[i][j][0]);
                C1[i][j][1] = fmaf(p0.y, INV256, C1[i][j][1]);
                C1[i][j][2] = fmaf(p1.x, INV256, C1[i][j][2]);
                C1[i][j][3] = fmaf(p1.y, INV256, C1[i][j][3]);
            }
        __syncthreads();
    }

    // ---- epilogue ----
    const int rr = lane >> 2;
    const int cc = (lane & 3) * 2;
    const float scl = (MODE == 0 && bz == 0) ? 0.1803368801111244f : 1.0f; // (1/8)*log2(e)
    #pragma unroll
    for (int i = 0; i < 2; ++i) {
        #pragma unroll
        for (int j = 0; j < 8; ++j) {
            int m1 = m0 + wm + i * 16 + rr;
            int m2 = m1 + 8;
            int n  = n0 + wn + j * 8 + cc;
            if (MODE == 0) {
                __half* oh = (bz == 0) ? g_qh : (bz == 1) ? g_kh : g_vh;
                __half* ol = (bz == 0) ? g_ql : (bz == 1) ? g_kl : g_vl;
                int head = n >> 6, hd = n & 63;
                #pragma unroll
                for (int half = 0; half < 2; ++half) {
                    int mm = half ? m2 : m1;
                    float v0 = C1[i][j][half * 2] * scl, v1 = C1[i][j][half * 2 + 1] * scl;
                    __half h0 = __float2half_rn(v0), h1 = __float2half_rn(v1);
                    float l0 = (v0 - __half2float(h0)) * 256.f;
                    float l1 = (v1 - __half2float(h1)) * 256.f;
                    int b = mm >> 11, s = mm & 2047;
                    size_t idx = (((size_t)(b * HH + head) * SS + s) * HD) + hd;
                    *(uint32_t*)&oh[idx] = packh2h(h0, h1);
                    *(uint32_t*)&ol[idx] = packh2(l0, l1);
                }
            } else {
                float b0 = bias[n], b1 = bias[n + 1];
                *(float2*)&dout[(size_t)m1 * DOUT + n] = make_float2(C1[i][j][0] + b0, C1[i][j][1] + b1);
                *(float2*)&dout[(size_t)m2 * DOUT + n] = make_float2(C1[i][j][2] + b0, C1[i][j][3] + b1);
            }
        }
    }
}

// ---------------------------------------------------------------------------
// Causal flash attention (fp16 hi/lo split, max-free softmax).
// CTA: 64 queries x (b,h), 128 threads, KV tiles of 32, 3 CTAs/SM.
// Main MMAs f32-acc; cross MMAs f16-acc, merged /256 per tile.
// ---------------------------------------------------------------------------
#define APITCH  144
#define QBYTES  (64 * APITCH)
#define KVB     (32 * APITCH)
#define OFF_ST  (2 * QBYTES)
#define STG_B   (4 * KVB)
#define ATTN_SMEM (OFF_ST + 2 * STG_B)  // 55296

__global__ __launch_bounds__(128, 3) void attn_mma_kernel()
{
    extern __shared__ char smc[];
    const uint32_t smb = smem_u32(smc);

    const int tid  = threadIdx.x;
    const int lane = tid & 31;
    const int wid  = tid >> 5;
    const int qt   = (int)(gridDim.x - 1) - (int)blockIdx.x;
    const int h    = blockIdx.y, b = blockIdx.z;
    const int wq   = wid * 16;

    const size_t bh = ((size_t)(b * HH + h)) * SS;
    const char* gqh = (const char*)(g_qh + (bh + (size_t)qt * 64) * HD);
    const char* gql = (const char*)(g_ql + (bh + (size_t)qt * 64) * HD);
    const char* gkh = (const char*)(g_kh + bh * HD);
    const char* gkl = (const char*)(g_kl + bh * HD);
    const char* gvh = (const char*)(g_vh + bh * HD);
    const char* gvl = (const char*)(g_vl + bh * HD);

    #pragma unroll
    for (int i = 0; i < 4; ++i) {
        int s = tid + i * 128;
        int r = s >> 3, seg = s & 7;
        uint32_t doff = r * APITCH + seg * 16;
        size_t   goff = (size_t)r * 128 + seg * 16;
        cp16(smb + doff,          gqh + goff);
        cp16(smb + QBYTES + doff, gql + goff);
    }
    auto loadKV = [&](int jt, int st) {
        const uint32_t base = smb + OFF_ST + st * STG_B;
        const size_t g0 = (size_t)jt * 32 * 128;
        #pragma unroll
        for (int i = 0; i < 2; ++i) {
            int s = tid + i * 128;
            int r = s >> 3, seg = s & 7;
            uint32_t doff = r * APITCH + seg * 16;
            size_t   goff = g0 + (size_t)r * 128 + seg * 16;
            cp16(base + doff,           gkh + goff);
            cp16(base + KVB + doff,     gkl + goff);
            cp16(base + 2 * KVB + doff, gvh + goff);
            cp16(base + 3 * KVB + doff, gvl + goff);
        }
    };
    loadKV(0, 0);
    cp_commit();

    uint32_t qh[4][4], ql[4][4];
    float O[8][4] = {};
    float rs0 = 0.f, rs1 = 0.f;

    const uint32_t aoff = (wq + (lane & 15)) * APITCH + (lane >> 4) * 16;
    const uint32_t krow = (((lane >> 4) << 3) + (lane & 7)) * APITCH + ((lane >> 3) & 1) * 16;
    const uint32_t vrow = (lane & 15) * APITCH + (lane >> 4) * 16;

    const int jmax = 2 * qt + 1;
    for (int jt = 0; jt <= jmax; ++jt) {
        const int st = jt & 1;
        if (jt < jmax) { loadKV(jt + 1, st ^ 1); cp_commit(); cp_wait1(); }
        else           { cp_wait0(); }
        __syncthreads();

        if (jt == 0) {
            #pragma unroll
            for (int f = 0; f < 4; ++f) {
                ldsm4(qh[f][0], qh[f][1], qh[f][2], qh[f][3], smb + aoff + f * 32);
                ldsm4(ql[f][0], ql[f][1], ql[f][2], ql[f][3], smb + QBYTES + aoff + f * 32);
            }
        }

        const bool active = !(jt == jmax && wq < 32);
        if (active) {
            const uint32_t kb = smb + OFF_ST + st * STG_B;

            // ---- S = Q K^T : main f32-acc + cross f16-acc ----
            float s_[4][4] = {};
            uint32_t c2[4][2] = {};
            #pragma unroll
            for (int f = 0; f < 4; ++f) {
                uint32_t kh[2][4], kl[2][4];
                #pragma unroll
                for (int jp = 0; jp < 2; ++jp) {
                    uint32_t a = kb + krow + jp * 16 * APITCH + f * 32;
                    ldsm4(kh[jp][0], kh[jp][1], kh[jp][2], kh[jp][3], a);
                    ldsm4(kl[jp][0], kl[jp][1], kl[jp][2], kl[jp][3], a + KVB);
                }
                #pragma unroll
                for (int jp = 0; jp < 2; ++jp) {
                    mma_f32(s_[2*jp],     qh[f], kh[jp]);
                    mma_f32(s_[2*jp + 1], qh[f], kh[jp] + 2);
                }
                #pragma unroll
                for (int jp = 0; jp < 2; ++jp) {
                    mma_f16(c2[2*jp],     ql[f], kh[jp]);
                    mma_f16(c2[2*jp + 1], ql[f], kh[jp] + 2);
                }
                #pragma unroll
                for (int jp = 0; jp < 2; ++jp) {
                    mma_f16(c2[2*jp],     qh[f], kl[jp]);
                    mma_f16(c2[2*jp + 1], qh[f], kl[jp] + 2);
                }
            }
            // merge cross (x256) into s_
            #pragma unroll
            for (int j = 0; j < 4; ++j) {
                float2 p0 = uph2(c2[j][0]);
                float2 p1 = uph2(c2[j][1]);
                s_[j][0] = fmaf(p0.x, INV256, s_[j][0]);
                s_[j][1] = fmaf(p0.y, INV256, s_[j][1]);
                s_[j][2] = fmaf(p1.x, INV256, s_[j][2]);
                s_[j][3] = fmaf(p1.y, INV256, s_[j][3]);
            }

            // ---- causal mask (diagonal region: jt >= 2*qt) ----
            if (jt >= 2 * qt) {
                const int qrow  = qt * 64 + wq + (lane >> 2);
                const int kcol0 = jt * 32 + (lane & 3) * 2;
                #pragma unroll
                for (int j = 0; j < 4; ++j) {
                    int c0 = kcol0 + j * 8, c1 = c0 + 1;
                    if (c0 > qrow)     s_[j][0] = -1e30f;
                    if (c1 > qrow)     s_[j][1] = -1e30f;
                    if (c0 > qrow + 8) s_[j][2] = -1e30f;
                    if (c1 > qrow + 8) s_[j][3] = -1e30f;
                }
            }

            // ---- max-free softmax ----
            #pragma unroll
            for (int j = 0; j < 4; ++j) {
                s_[j][0] = exp2f(s_[j][0]);
                s_[j][1] = exp2f(s_[j][1]);
                s_[j][2] = exp2f(s_[j][2]);
                s_[j][3] = exp2f(s_[j][3]);
                rs0 += s_[j][0] + s_[j][1];
                rs1 += s_[j][2] + s_[j][3];
            }

            // ---- O += P V : main f32-acc + cross f16-acc (merged per tile) ----
            const uint32_t vb = kb + 2 * KVB + vrow;
            uint32_t oc[8][2] = {};
            #pragma unroll
            for (int f = 0; f < 2; ++f) {
                uint32_t ph[4], pl[4];
                #pragma unroll
                for (int t = 0; t < 2; ++t) {
                    float p0 = s_[2*f + t][0], p1 = s_[2*f + t][1];
                    float p2 = s_[2*f + t][2], p3 = s_[2*f + t][3];
                    __half h0 = __float2half_rn(p0), h1 = __float2half_rn(p1);
                    __half h2 = __float2half_rn(p2), h3 = __float2half_rn(p3);
                    ph[2*t]   = packh2h(h0, h1);
                    ph[2*t+1] = packh2h(h2, h3);
                    pl[2*t]   = packh2((p0 - __half2float(h0)) * 256.f,
                                       (p1 - __half2float(h1)) * 256.f);
                    pl[2*t+1] = packh2((p2 - __half2float(h2)) * 256.f,
                                       (p3 - __half2float(h3)) * 256.f);
                }
                const uint32_t va = vb + f * 16 * APITCH;
                uint32_t vh[4][4], vl[4][4];
                #pragma unroll
                for (int dj = 0; dj < 4; ++dj) {
                    ldsm4t(vh[dj][0], vh[dj][1], vh[dj][2], vh[dj][3], va + dj * 32);
                    ldsm4t(vl[dj][0], vl[dj][1], vl[dj][2], vl[dj][3], va + dj * 32 + KVB);
                }
                #pragma unroll
                for (int dj = 0; dj < 4; ++dj) {
                    mma_f32(O[2*dj],     ph, vh[dj]);
                    mma_f32(O[2*dj + 1], ph, vh[dj] + 2);
                }
                #pragma unroll
                for (int dj = 0; dj < 4; ++dj) {
                    mma_f16(oc[2*dj],     pl, vh[dj]);
                    mma_f16(oc[2*dj + 1], pl, vh[dj] + 2);
                }
                #pragma unroll
                for (int dj = 0; dj < 4; ++dj) {
                    mma_f16(oc[2*dj],     ph, vl[dj]);
                    mma_f16(oc[2*dj + 1], ph, vl[dj] + 2);
                }
            }
            // merge PV cross (x256) into O
            #pragma unroll
            for (int dj = 0; dj < 8; ++dj) {
                float2 p0 = uph2(oc[dj][0]);
                float2 p1 = uph2(oc[dj][1]);
                O[dj][0] = fmaf(p0.x, INV256, O[dj][0]);
                O[dj][1] = fmaf(p0.y, INV256, O[dj][1]);
                O[dj][2] = fmaf(p1.x, INV256, O[dj][2]);
                O[dj][3] = fmaf(p1.y, INV256, O[dj][3]);
            }
        }
        __syncthreads();
    }

    // ---- finalize: quad-reduce row sums once, normalize, write ctx limbs ----
    rs0 += __shfl_xor_sync(0xffffffffu, rs0, 1);
    rs0 += __shfl_xor_sync(0xffffffffu, rs0, 2);
    rs1 += __shfl_xor_sync(0xffffffffu, rs1, 1);
    rs1 += __shfl_xor_sync(0xffffffffu, rs1, 2);
    const float inv0 = 1.0f / rs0, inv1 = 1.0f / rs1;

    const int r    = lane >> 2;
    const int dcol = (lane & 3) * 2;
    const int row0 = qt * 64 + wq + r;
    const size_t base0 = ((size_t)b * SS + row0) * DOUT + h * 64;
    const size_t base1 = base0 + (size_t)8 * DOUT;
    #pragma unroll
    for (int dj = 0; dj < 8; ++dj) {
        int d = dj * 8 + dcol;
        {
            float v0 = O[dj][0] * inv0, v1 = O[dj][1] * inv0;
            __half h0 = __float2half_rn(v0), h1 = __float2half_rn(v1);
            *(uint32_t*)&g_cxh[base0 + d] = packh2h(h0, h1);
            *(uint32_t*)&g_cxl[base0 + d] = packh2((v0 - __half2float(h0)) * 256.f,
                                                   (v1 - __half2float(h1)) * 256.f);
        }
        {
            float v2 = O[dj][2] * inv1, v3 = O[dj][3] * inv1;
            __half h2 = __float2half_rn(v2), h3 = __float2half_rn(v3);
            *(uint32_t*)&g_cxh[base1 + d] = packh2h(h2, h3);
            *(uint32_t*)&g_cxl[base1 + d] = packh2((v2 - __half2float(h2)) * 256.f,
                                                   (v3 - __half2float(h3)) * 256.f);
        }
    }
}

// ---------------------------------------------------------------------------
extern "C" void kernel_launch(void* const* d_in, const int* in_sizes, int n_in,
                              void* d_out, int out_size)
{
    const float* x  = (const float*)d_in[0];
    const float* Wq = (const float*)d_in[1];
    const float* Wk = (const float*)d_in[2];
    const float* Wv = (const float*)d_in[3];
    const float* Wo = (const float*)d_in[4];
    const float* bo = (const float*)d_in[5];
    float* out = (float*)d_out;

    cudaFuncSetAttribute(mma_gemm<0>, cudaFuncAttributeMaxDynamicSharedMemorySize, GSMEM);
    cudaFuncSetAttribute(mma_gemm<1>, cudaFuncAttributeMaxDynamicSharedMemorySize, GSMEM);
    cudaFuncSetAttribute(attn_mma_kernel, cudaFuncAttributeMaxDynamicSharedMemorySize, ATTN_SMEM);

    conv_x_kernel<<<BB * SS * DIN / 1024, 256>>>(x);
    conv_w_kernel<<<dim3(32, 32, 4), dim3(32, 8)>>>(Wq, Wk, Wv, Wo);
    mma_gemm<0><<<dim3(128, 8, 3), 128, GSMEM>>>(nullptr, nullptr);
    attn_mma_kernel<<<dim3(32, HH, BB), 128, ATTN_SMEM>>>();
    mma_gemm<1><<<dim3(128, 8), 128, GSMEM>>>(bo, out);
}

// round 13
// speedup vs baseline: 1.1104x; 1.1104x over previous
#include <cuda_runtime.h>
#include <cuda_bf16.h>
#include <cstdint>

#define BB   4
#define HH   16
#define SS   2048
#define HD   64
#define DIN  1024
#define DOUT 1024

// ---------------------------------------------------------------------------
// Scratch (__device__ globals; no allocations allowed)
// ---------------------------------------------------------------------------
__device__ __nv_bfloat16 g_xh[BB * SS * DIN];        // x hi/lo bf16
__device__ __nv_bfloat16 g_xl[BB * SS * DIN];
__device__ __nv_bfloat16 g_wth[4 * DIN * DOUT];      // W^T hi/lo bf16 [n][k]
__device__ __nv_bfloat16 g_wtl[4 * DIN * DOUT];
__device__ __nv_bfloat16 g_qh[BB * HH * SS * HD];    // Q (pre-scaled) hi/lo [B,H,S,HD]
__device__ __nv_bfloat16 g_ql[BB * HH * SS * HD];
__device__ __nv_bfloat16 g_kh[BB * HH * SS * HD];
__device__ __nv_bfloat16 g_kl[BB * HH * SS * HD];
__device__ __nv_bfloat16 g_vh[BB * HH * SS * HD];
__device__ __nv_bfloat16 g_vl[BB * HH * SS * HD];
__device__ __nv_bfloat16 g_cxh[BB * SS * DOUT];      // ctx hi/lo [8192][1024]
__device__ __nv_bfloat16 g_cxl[BB * SS * DOUT];

// ---------------------------------------------------------------------------
// Helpers
// ---------------------------------------------------------------------------
__device__ __forceinline__ uint32_t smem_u32(const void* p) {
    uint32_t a;
    asm("{ .reg .u64 t; cvta.to.shared.u64 t, %1; cvt.u32.u64 %0, t; }" : "=r"(a) : "l"(p));
    return a;
}
__device__ __forceinline__ float ex2(float x) {
    float y;
    asm("ex2.approx.f32 %0, %1;" : "=f"(y) : "f"(x));
    return y;
}
__device__ __forceinline__ uint32_t pack_bf16(float a, float b) {
    __nv_bfloat162 t = __floats2bfloat162_rn(a, b);
    return *(uint32_t*)&t;
}
__device__ __forceinline__ uint32_t pack2h(__nv_bfloat16 x, __nv_bfloat16 y) {
    __nv_bfloat162 t; t.x = x; t.y = y;
    return *(uint32_t*)&t;
}
__device__ __forceinline__ void ldsm4(uint32_t& r0, uint32_t& r1, uint32_t& r2, uint32_t& r3,
                                      uint32_t addr) {
    asm volatile("ldmatrix.sync.aligned.m8n8.x4.shared.b16 {%0,%1,%2,%3}, [%4];"
                 : "=r"(r0), "=r"(r1), "=r"(r2), "=r"(r3) : "r"(addr));
}
__device__ __forceinline__ void ldsm4t(uint32_t& r0, uint32_t& r1, uint32_t& r2, uint32_t& r3,
                                       uint32_t addr) {
    asm volatile("ldmatrix.sync.aligned.m8n8.x4.trans.shared.b16 {%0,%1,%2,%3}, [%4];"
                 : "=r"(r0), "=r"(r1), "=r"(r2), "=r"(r3) : "r"(addr));
}
__device__ __forceinline__ void mma16816(float* c, const uint32_t* a, const uint32_t* b) {
    asm volatile(
        "mma.sync.aligned.m16n8k16.row.col.f32.bf16.bf16.f32 "
        "{%0,%1,%2,%3}, {%4,%5,%6,%7}, {%8,%9}, {%0,%1,%2,%3};"
        : "+f"(c[0]), "+f"(c[1]), "+f"(c[2]), "+f"(c[3])
        : "r"(a[0]), "r"(a[1]), "r"(a[2]), "r"(a[3]), "r"(b[0]), "r"(b[1]));
}
__device__ __forceinline__ void cp16(uint32_t dst, const void* src) {
    asm volatile("cp.async.cg.shared.global [%0], [%1], 16;" :: "r"(dst), "l"(src));
}
__device__ __forceinline__ void cp_commit() { asm volatile("cp.async.commit_group;" ::: "memory"); }
__device__ __forceinline__ void cp_wait1()  { asm volatile("cp.async.wait_group 1;" ::: "memory"); }
__device__ __forceinline__ void cp_wait0()  { asm volatile("cp.async.wait_group 0;" ::: "memory"); }

// ---------------------------------------------------------------------------
// Merged conversion kernel: blocks [0, 8192) convert x; [8192, 12288) convert W.
// ---------------------------------------------------------------------------
__global__ __launch_bounds__(256) void conv_all_kernel(
    const float* __restrict__ x,
    const float* __restrict__ Wq, const float* __restrict__ Wk,
    const float* __restrict__ Wv, const float* __restrict__ Wo)
{
    __shared__ float t[32][33];
    if (blockIdx.x < 8192) {
        int i = (blockIdx.x * 256 + threadIdx.x) * 4;
        float4 v = *(const float4*)(x + i);
        __nv_bfloat16 h0 = __float2bfloat16(v.x), h1 = __float2bfloat16(v.y);
        __nv_bfloat16 h2 = __float2bfloat16(v.z), h3 = __float2bfloat16(v.w);
        float l0 = v.x - __bfloat162float(h0), l1 = v.y - __bfloat162float(h1);
        float l2 = v.z - __bfloat162float(h2), l3 = v.w - __bfloat162float(h3);
        *(uint2*)&g_xh[i] = make_uint2(pack2h(h0, h1), pack2h(h2, h3));
        *(uint2*)&g_xl[i] = make_uint2(pack_bf16(l0, l1), pack_bf16(l2, l3));
    } else {
        const int w = blockIdx.x - 8192;
        const int z = w >> 10;
        const int b2 = w & 1023;
        const int n0 = (b2 & 31) * 32;
        const int k0 = (b2 >> 5) * 32;
        const float* W = (z == 0) ? Wq : (z == 1) ? Wk : (z == 2) ? Wv : Wo;
        const int tx = threadIdx.x & 31, ty = threadIdx.x >> 5;   // 32 x 8
        #pragma unroll
        for (int i = 0; i < 4; ++i)
            t[ty + i * 8][tx] = W[(size_t)(k0 + ty + i * 8) * DOUT + n0 + tx];
        __syncthreads();
        __nv_bfloat16* wh = g_wth + (size_t)z * DIN * DOUT;
        __nv_bfloat16* wl = g_wtl + (size_t)z * DIN * DOUT;
        #pragma unroll
        for (int i = 0; i < 4; ++i) {
            int n = n0 + ty + i * 8, k = k0 + tx;
            float v = t[tx][ty + i * 8];                 // = W[k][n]
            __nv_bfloat16 h = __float2bfloat16(v);
            wh[(size_t)n * DIN + k] = h;
            wl[(size_t)n * DIN + k] = __float2bfloat16(v - __bfloat162float(h));
        }
    }
}

// ---------------------------------------------------------------------------
// bf16 hi/lo split GEMM via mma.sync.  CTA 64x128, 128 threads (warp 32x64),
// K-chunks of 32, 2 stages, split-term-outer MMA ordering, 3 CTAs/SM.
// MODE 0: A = x, B = W^T[z] -> Q/K/V bf16 hi/lo [B,H,S,HD] (Q pre-scaled).
// MODE 1: A = ctx, B = Wo^T, +bias -> d_out fp32.
// ---------------------------------------------------------------------------
#define KC     32
#define PITCH  80
#define ATILE  (64 * PITCH)              // 5120
#define BTILE  (128 * PITCH)             // 10240
#define STAGEB (2 * ATILE + 2 * BTILE)   // 30720 (Ah, Al, Bh, Bl)
#define GSMEM  (2 * STAGEB)              // 61440 -> 3 CTAs/SM

template<int MODE>
__global__ __launch_bounds__(128, 3) void mma_gemm(const float* __restrict__ bias,
                                                   float* __restrict__ dout)
{
    extern __shared__ char smc[];
    const uint32_t smb = smem_u32(smc);

    const int tid  = threadIdx.x;
    const int lane = tid & 31;
    const int wid  = tid >> 5;
    const int wm   = (wid & 1) * 32;
    const int wn   = (wid >> 1) * 64;

    const int m0 = blockIdx.x * 64;
    const int n0 = blockIdx.y * 128;
    const int bz = (MODE == 0) ? blockIdx.z : 3;

    const __nv_bfloat16* Ah = (MODE == 0) ? g_xh : g_cxh;
    const __nv_bfloat16* Al = (MODE == 0) ? g_xl : g_cxl;
    const __nv_bfloat16* Bh = g_wth + (size_t)bz * DIN * DOUT;
    const __nv_bfloat16* Bl = g_wtl + (size_t)bz * DIN * DOUT;

    const char* agh = (const char*)Ah + ((size_t)m0 * DIN) * 2;
    const char* agl = (const char*)Al + ((size_t)m0 * DIN) * 2;
    const char* bgh = (const char*)Bh + ((size_t)n0 * DIN) * 2;
    const char* bgl = (const char*)Bl + ((size_t)n0 * DIN) * 2;

    auto load = [&](int c, int st) {
        const uint32_t base = smb + st * STAGEB;
        const size_t cko = (size_t)c * KC * 2;       // 64B of k per chunk-row
        #pragma unroll
        for (int i = 0; i < 2; ++i) {
            int s   = tid + i * 128;
            int r   = s >> 2;
            int seg = s & 3;
            size_t  go  = (size_t)r * (DIN * 2) + cko + seg * 16;
            uint32_t dof = r * PITCH + seg * 16;
            cp16(base + dof,         agh + go);
            cp16(base + ATILE + dof, agl + go);
        }
        #pragma unroll
        for (int i = 0; i < 4; ++i) {
            int s   = tid + i * 128;
            int r   = s >> 2;
            int seg = s & 3;
            size_t  go  = (size_t)r * (DIN * 2) + cko + seg * 16;
            uint32_t dof = r * PITCH + seg * 16;
            cp16(base + 2 * ATILE + dof,         bgh + go);
            cp16(base + 2 * ATILE + BTILE + dof, bgl + go);
        }
    };

    float C[2][8][4] = {};

    const uint32_t aRow = wm + (lane & 15);
    const uint32_t aCol = (lane >> 4) * 16;
    const uint32_t bRow = wn + ((lane >> 4) << 3) + (lane & 7);
    const uint32_t bCol = ((lane >> 3) & 1) * 16;

    load(0, 0);
    cp_commit();

    for (int c = 0; c < DIN / KC; ++c) {
        const int st = c & 1;
        if (c + 1 < DIN / KC) { load(c + 1, st ^ 1); cp_commit(); cp_wait1(); }
        else                  { cp_wait0(); }
        __syncthreads();

        const uint32_t sA = smb + st * STAGEB;
        const uint32_t sB = sA + 2 * ATILE;

        #pragma unroll
        for (int ks = 0; ks < 2; ++ks) {
            uint32_t ah[2][4], al[2][4], bh[8][2], bl[8][2];
            #pragma unroll
            for (int i = 0; i < 2; ++i) {
                uint32_t ad = sA + (aRow + i * 16) * PITCH + ks * 32 + aCol;
                ldsm4(ah[i][0], ah[i][1], ah[i][2], ah[i][3], ad);
                ldsm4(al[i][0], al[i][1], al[i][2], al[i][3], ad + ATILE);
            }
            #pragma unroll
            for (int p = 0; p < 4; ++p) {
                uint32_t bd = sB + (bRow + p * 16) * PITCH + ks * 32 + bCol;
                ldsm4(bh[2*p][0], bh[2*p][1], bh[2*p+1][0], bh[2*p+1][1], bd);
                ldsm4(bl[2*p][0], bl[2*p][1], bl[2*p+1][0], bl[2*p+1][1], bd + BTILE);
            }
            // split-term-outer ordering: 16 independent MMAs per pass
            #pragma unroll
            for (int i = 0; i < 2; ++i)
                #pragma unroll
                for (int j = 0; j < 8; ++j)
                    mma16816(C[i][j], ah[i], bh[j]);
            #pragma unroll
            for (int i = 0; i < 2; ++i)
                #pragma unroll
                for (int j = 0; j < 8; ++j)
                    mma16816(C[i][j], ah[i], bl[j]);
            #pragma unroll
            for (int i = 0; i < 2; ++i)
                #pragma unroll
                for (int j = 0; j < 8; ++j)
                    mma16816(C[i][j], al[i], bh[j]);
        }
        __syncthreads();
    }

    // ---- epilogue ----
    const int rr = lane >> 2;
    const int cc = (lane & 3) * 2;
    const float scl = (MODE == 0 && bz == 0) ? 0.1803368801111244f : 1.0f; // (1/8)*log2(e)
    #pragma unroll
    for (int i = 0; i < 2; ++i) {
        #pragma unroll
        for (int j = 0; j < 8; ++j) {
            int m1 = m0 + wm + i * 16 + rr;
            int m2 = m1 + 8;
            int n  = n0 + wn + j * 8 + cc;
            if (MODE == 0) {
                __nv_bfloat16* oh = (bz == 0) ? g_qh : (bz == 1) ? g_kh : g_vh;
                __nv_bfloat16* ol = (bz == 0) ? g_ql : (bz == 1) ? g_kl : g_vl;
                int head = n >> 6, hd = n & 63;
                #pragma unroll
                for (int half = 0; half < 2; ++half) {
                    int mm = half ? m2 : m1;
                    float v0 = C[i][j][half * 2] * scl, v1 = C[i][j][half * 2 + 1] * scl;
                    __nv_bfloat16 h0 = __float2bfloat16(v0), h1 = __float2bfloat16(v1);
                    float l0 = v0 - __bfloat162float(h0), l1 = v1 - __bfloat162float(h1);
                    int b = mm >> 11, s = mm & 2047;
                    size_t idx = (((size_t)(b * HH + head) * SS + s) * HD) + hd;
                    *(uint32_t*)&oh[idx] = pack2h(h0, h1);
                    *(uint32_t*)&ol[idx] = pack_bf16(l0, l1);
                }
            } else {
                float b0 = bias[n], b1 = bias[n + 1];
                *(float2*)&dout[(size_t)m1 * DOUT + n] = make_float2(C[i][j][0] + b0, C[i][j][1] + b1);
                *(float2*)&dout[(size_t)m2 * DOUT + n] = make_float2(C[i][j][2] + b0, C[i][j][3] + b1);
            }
        }
    }
}

// ---------------------------------------------------------------------------
// Tensor-core causal flash attention (bf16 hi/lo split, max-free softmax).
// CTA: 64 queries x (b,h), 128 threads.  KV tiles of 32, cp.async x2 stages.
// 3 CTAs/SM.  ex2.approx softmax.
// ---------------------------------------------------------------------------
#define APITCH  144
#define QBYTES  (64 * APITCH)
#define KVB     (32 * APITCH)
#define OFF_ST  (2 * QBYTES)
#define STG_B   (4 * KVB)
#define ATTN_SMEM (OFF_ST + 2 * STG_B)  // 55296

__global__ __launch_bounds__(128, 3) void attn_mma_kernel()
{
    extern __shared__ char smc[];
    const uint32_t smb = smem_u32(smc);

    const int tid  = threadIdx.x;
    const int lane = tid & 31;
    const int wid  = tid >> 5;
    const int qt   = (int)(gridDim.x - 1) - (int)blockIdx.x;  // heavy tiles first
    const int h    = blockIdx.y, b = blockIdx.z;
    const int wq   = wid * 16;

    const size_t bh = ((size_t)(b * HH + h)) * SS;
    const char* gqh = (const char*)(g_qh + (bh + (size_t)qt * 64) * HD);
    const char* gql = (const char*)(g_ql + (bh + (size_t)qt * 64) * HD);
    const char* gkh = (const char*)(g_kh + bh * HD);
    const char* gkl = (const char*)(g_kl + bh * HD);
    const char* gvh = (const char*)(g_vh + bh * HD);
    const char* gvl = (const char*)(g_vl + bh * HD);

    #pragma unroll
    for (int i = 0; i < 4; ++i) {
        int s = tid + i * 128;
        int r = s >> 3, seg = s & 7;
        uint32_t doff = r * APITCH + seg * 16;
        size_t   goff = (size_t)r * 128 + seg * 16;
        cp16(smb + doff,          gqh + goff);
        cp16(smb + QBYTES + doff, gql + goff);
    }
    auto loadKV = [&](int jt, int st) {
        const uint32_t base = smb + OFF_ST + st * STG_B;
        const size_t g0 = (size_t)jt * 32 * 128;
        #pragma unroll
        for (int i = 0; i < 2; ++i) {
            int s = tid + i * 128;
            int r = s >> 3, seg = s & 7;
            uint32_t doff = r * APITCH + seg * 16;
            size_t   goff = g0 + (size_t)r * 128 + seg * 16;
            cp16(base + doff,           gkh + goff);
            cp16(base + KVB + doff,     gkl + goff);
            cp16(base + 2 * KVB + doff, gvh + goff);
            cp16(base + 3 * KVB + doff, gvl + goff);
        }
    };
    loadKV(0, 0);
    cp_commit();

    uint32_t qh[4][4], ql[4][4];
    float O[8][4] = {};
    float rs0 = 0.f, rs1 = 0.f;

    const uint32_t aoff = (wq + (lane & 15)) * APITCH + (lane >> 4) * 16;
    const uint32_t krow = (((lane >> 4) << 3) + (lane & 7)) * APITCH + ((lane >> 3) & 1) * 16;
    const uint32_t vrow = (lane & 15) * APITCH + (lane >> 4) * 16;

    const int jmax = 2 * qt + 1;
    for (int jt = 0; jt <= jmax; ++jt) {
        const int st = jt & 1;
        if (jt < jmax) { loadKV(jt + 1, st ^ 1); cp_commit(); cp_wait1(); }
        else           { cp_wait0(); }
        __syncthreads();

        if (jt == 0) {
            #pragma unroll
            for (int f = 0; f < 4; ++f) {
                ldsm4(qh[f][0], qh[f][1], qh[f][2], qh[f][3], smb + aoff + f * 32);
                ldsm4(ql[f][0], ql[f][1], ql[f][2], ql[f][3], smb + QBYTES + aoff + f * 32);
            }
        }

        const bool active = !(jt == jmax && wq < 32);
        if (active) {
            const uint32_t kb = smb + OFF_ST + st * STG_B;

            float s_[4][4] = {};
            #pragma unroll
            for (int f = 0; f < 4; ++f) {
                uint32_t kh[2][4], kl[2][4];
                #pragma unroll
                for (int jp = 0; jp < 2; ++jp) {
                    uint32_t a = kb + krow + jp * 16 * APITCH + f * 32;
                    ldsm4(kh[jp][0], kh[jp][1], kh[jp][2], kh[jp][3], a);
                    ldsm4(kl[jp][0], kl[jp][1], kl[jp][2], kl[jp][3], a + KVB);
                }
                #pragma unroll
                for (int jp = 0; jp < 2; ++jp) {
                    mma16816(s_[2*jp],     qh[f], kh[jp]);
                    mma16816(s_[2*jp + 1], qh[f], kh[jp] + 2);
                }
                #pragma unroll
                for (int jp = 0; jp < 2; ++jp) {
                    mma16816(s_[2*jp],     ql[f], kh[jp]);
                    mma16816(s_[2*jp + 1], ql[f], kh[jp] + 2);
                }
                #pragma unroll
                for (int jp = 0; jp < 2; ++jp) {
                    mma16816(s_[2*jp],     qh[f], kl[jp]);
                    mma16816(s_[2*jp + 1], qh[f], kl[jp] + 2);
                }
            }

            if (jt >= 2 * qt) {
                const int qrow  = qt * 64 + wq + (lane >> 2);
                const int kcol0 = jt * 32 + (lane & 3) * 2;
                #pragma unroll
                for (int j = 0; j < 4; ++j) {
                    int c0 = kcol0 + j * 8, c1 = c0 + 1;
                    if (c0 > qrow)     s_[j][0] = -1e30f;
                    if (c1 > qrow)     s_[j][1] = -1e30f;
                    if (c0 > qrow + 8) s_[j][2] = -1e30f;
                    if (c1 > qrow + 8) s_[j][3] = -1e30f;
                }
            }

            // max-free softmax with raw MUFU.EX2
            #pragma unroll
            for (int j = 0; j < 4; ++j) {
                s_[j][0] = ex2(s_[j][0]);
                s_[j][1] = ex2(s_[j][1]);
                s_[j][2] = ex2(s_[j][2]);
                s_[j][3] = ex2(s_[j][3]);
                rs0 += s_[j][0] + s_[j][1];
                rs1 += s_[j][2] + s_[j][3];
            }

            const uint32_t vb = kb + 2 * KVB + vrow;
            #pragma unroll
            for (int f = 0; f < 2; ++f) {
                uint32_t ph[4], pl[4];
                #pragma unroll
                for (int t = 0; t < 2; ++t) {
                    float p0 = s_[2*f + t][0], p1 = s_[2*f + t][1];
                    float p2 = s_[2*f + t][2], p3 = s_[2*f + t][3];
                    __nv_bfloat16 h0 = __float2bfloat16(p0), h1 = __float2bfloat16(p1);
                    __nv_bfloat16 h2 = __float2bfloat16(p2), h3 = __float2bfloat16(p3);
                    ph[2*t]   = pack2h(h0, h1);
                    ph[2*t+1] = pack2h(h2, h3);
                    pl[2*t]   = pack_bf16(p0 - __bfloat162float(h0), p1 - __bfloat162float(h1));
                    pl[2*t+1] = pack_bf16(p2 - __bfloat162float(h2), p3 - __bfloat162float(h3));
                }
                const uint32_t va = vb + f * 16 * APITCH;
                uint32_t vh[4][4], vl[4][4];
                #pragma unroll
                for (int dj = 0; dj < 4; ++dj) {
                    ldsm4t(vh[dj][0], vh[dj][1], vh[dj][2], vh[dj][3], va + dj * 32);
                    ldsm4t(vl[dj][0], vl[dj][1], vl[dj][2], vl[dj][3], va + dj * 32 + KVB);
                }
                #pragma unroll
                for (int dj = 0; dj < 4; ++dj) {
                    mma16816(O[2*dj],     ph, vh[dj]);
                    mma16816(O[2*dj + 1], ph, vh[dj] + 2);
                }
                #pragma unroll
                for (int dj = 0; dj < 4; ++dj) {
                    mma16816(O[2*dj],     pl, vh[dj]);
                    mma16816(O[2*dj + 1], pl, vh[dj] + 2);
                }
                #pragma unroll
                for (int dj = 0; dj < 4; ++dj) {
                    mma16816(O[2*dj],     ph, vl[dj]);
                    mma16816(O[2*dj + 1], ph, vl[dj] + 2);
                }
            }
        }
        __syncthreads();
    }

    // ---- finalize: quad-reduce row sums once, normalize, write ctx hi/lo ----
    rs0 += __shfl_xor_sync(0xffffffffu, rs0, 1);
    rs0 += __shfl_xor_sync(0xffffffffu, rs0, 2);
    rs1 += __shfl_xor_sync(0xffffffffu, rs1, 1);
    rs1 += __shfl_xor_sync(0xffffffffu, rs1, 2);
    const float inv0 = 1.0f / rs0, inv1 = 1.0f / rs1;

    const int r    = lane >> 2;
    const int dcol = (lane & 3) * 2;
    const int row0 = qt * 64 + wq + r;
    const size_t base0 = ((size_t)b * SS + row0) * DOUT + h * 64;
    const size_t base1 = base0 + (size_t)8 * DOUT;
    #pragma unroll
    for (int dj = 0; dj < 8; ++dj) {
        int d = dj * 8 + dcol;
        {
            float v0 = O[dj][0] * inv0, v1 = O[dj][1] * inv0;
            __nv_bfloat16 h0 = __float2bfloat16(v0), h1 = __float2bfloat16(v1);
            *(uint32_t*)&g_cxh[base0 + d] = pack2h(h0, h1);
            *(uint32_t*)&g_cxl[base0 + d] =
                pack_bf16(v0 - __bfloat162float(h0), v1 - __bfloat162float(h1));
        }
        {
            float v2 = O[dj][2] * inv1, v3 = O[dj][3] * inv1;
            __nv_bfloat16 h2 = __float2bfloat16(v2), h3 = __float2bfloat16(v3);
            *(uint32_t*)&g_cxh[base1 + d] = pack2h(h2, h3);
            *(uint32_t*)&g_cxl[base1 + d] =
                pack_bf16(v2 - __bfloat162float(h2), v3 - __bfloat162float(h3));
        }
    }
}

// ---------------------------------------------------------------------------
extern "C" void kernel_launch(void* const* d_in, const int* in_sizes, int n_in,
                              void* d_out, int out_size)
{
    const float* x  = (const float*)d_in[0];
    const float* Wq = (const float*)d_in[1];
    const float* Wk = (const float*)d_in[2];
    const float* Wv = (const float*)d_in[3];
    const float* Wo = (const float*)d_in[4];
    const float* bo = (const float*)d_in[5];
    float* out = (float*)d_out;

    cudaFuncSetAttribute(mma_gemm<0>, cudaFuncAttributeMaxDynamicSharedMemorySize, GSMEM);
    cudaFuncSetAttribute(mma_gemm<1>, cudaFuncAttributeMaxDynamicSharedMemorySize, GSMEM);
    cudaFuncSetAttribute(attn_mma_kernel, cudaFuncAttributeMaxDynamicSharedMemorySize, ATTN_SMEM);

    conv_all_kernel<<<12288, 256>>>(x, Wq, Wk, Wv, Wo);
    mma_gemm<0><<<dim3(128, 8, 3), 128, GSMEM>>>(nullptr, nullptr);
    attn_mma_kernel<<<dim3(32, HH, BB), 128, ATTN_SMEM>>>();
    mma_gemm<1><<<dim3(128, 8), 128, GSMEM>>>(bo, out);
}

// round 14
// speedup vs baseline: 1.3361x; 1.2033x over previous
#include <cuda_runtime.h>
#include <cuda_fp16.h>
#include <cstdint>

#define BB   4
#define HH   16
#define SS   2048
#define HD   64
#define DIN  1024
#define DOUT 1024

// ---------------------------------------------------------------------------
// Scratch (__device__ globals; no allocations allowed).  fp16 limbs.
// ---------------------------------------------------------------------------
__device__ __half g_xh[BB * SS * DIN];
__device__ __half g_xl[BB * SS * DIN];
__device__ __half g_wth[4 * DIN * DOUT];     // W^T hi [n][k]
__device__ __half g_wtl[4 * DIN * DOUT];     // W^T lo (used by Q,K gemms only)
__device__ __half g_qh[BB * HH * SS * HD];   // Q (pre-scaled) hi/lo [B,H,S,HD]
__device__ __half g_ql[BB * HH * SS * HD];
__device__ __half g_kh[BB * HH * SS * HD];
__device__ __half g_kl[BB * HH * SS * HD];
__device__ __half g_vh[BB * HH * SS * HD];   // V: single fp16 (value path)
__device__ __half g_cxh[BB * SS * DOUT];     // ctx hi/lo [8192][1024]
__device__ __half g_cxl[BB * SS * DOUT];

// ---------------------------------------------------------------------------
// Helpers
// ---------------------------------------------------------------------------
__device__ __forceinline__ uint32_t smem_u32(const void* p) {
    uint32_t a;
    asm("{ .reg .u64 t; cvta.to.shared.u64 t, %1; cvt.u32.u64 %0, t; }" : "=r"(a) : "l"(p));
    return a;
}
__device__ __forceinline__ float ex2(float x) {
    float y;
    asm("ex2.approx.f32 %0, %1;" : "=f"(y) : "f"(x));
    return y;
}
__device__ __forceinline__ uint32_t packh2(float a, float b) {
    __half2 t = __floats2half2_rn(a, b);
    return *(uint32_t*)&t;
}
__device__ __forceinline__ uint32_t packh2h(__half a, __half b) {
    __half2 t = __halves2half2(a, b);
    return *(uint32_t*)&t;
}
__device__ __forceinline__ void ldsm4(uint32_t& r0, uint32_t& r1, uint32_t& r2, uint32_t& r3,
                                      uint32_t addr) {
    asm volatile("ldmatrix.sync.aligned.m8n8.x4.shared.b16 {%0,%1,%2,%3}, [%4];"
                 : "=r"(r0), "=r"(r1), "=r"(r2), "=r"(r3) : "r"(addr));
}
__device__ __forceinline__ void ldsm4t(uint32_t& r0, uint32_t& r1, uint32_t& r2, uint32_t& r3,
                                       uint32_t addr) {
    asm volatile("ldmatrix.sync.aligned.m8n8.x4.trans.shared.b16 {%0,%1,%2,%3}, [%4];"
                 : "=r"(r0), "=r"(r1), "=r"(r2), "=r"(r3) : "r"(addr));
}
__device__ __forceinline__ void mma16816(float* c, const uint32_t* a, const uint32_t* b) {
    asm volatile(
        "mma.sync.aligned.m16n8k16.row.col.f32.f16.f16.f32 "
        "{%0,%1,%2,%3}, {%4,%5,%6,%7}, {%8,%9}, {%0,%1,%2,%3};"
        : "+f"(c[0]), "+f"(c[1]), "+f"(c[2]), "+f"(c[3])
        : "r"(a[0]), "r"(a[1]), "r"(a[2]), "r"(a[3]), "r"(b[0]), "r"(b[1]));
}
__device__ __forceinline__ void cp16(uint32_t dst, const void* src) {
    asm volatile("cp.async.cg.shared.global [%0], [%1], 16;" :: "r"(dst), "l"(src));
}
__device__ __forceinline__ void cp_commit() { asm volatile("cp.async.commit_group;" ::: "memory"); }
__device__ __forceinline__ void cp_wait1()  { asm volatile("cp.async.wait_group 1;" ::: "memory"); }
__device__ __forceinline__ void cp_wait0()  { asm volatile("cp.async.wait_group 0;" ::: "memory"); }

// ---------------------------------------------------------------------------
// Merged conversion kernel: blocks [0, 8192) convert x; [8192, 12288) convert W.
// ---------------------------------------------------------------------------
__global__ __launch_bounds__(256) void conv_all_kernel(
    const float* __restrict__ x,
    const float* __restrict__ Wq, const float* __restrict__ Wk,
    const float* __restrict__ Wv, const float* __restrict__ Wo)
{
    __shared__ float t[32][33];
    if (blockIdx.x < 8192) {
        int i = (blockIdx.x * 256 + threadIdx.x) * 4;
        float4 v = *(const float4*)(x + i);
        __half h0 = __float2half_rn(v.x), h1 = __float2half_rn(v.y);
        __half h2 = __float2half_rn(v.z), h3 = __float2half_rn(v.w);
        float l0 = v.x - __half2float(h0), l1 = v.y - __half2float(h1);
        float l2 = v.z - __half2float(h2), l3 = v.w - __half2float(h3);
        *(uint2*)&g_xh[i] = make_uint2(packh2h(h0, h1), packh2h(h2, h3));
        *(uint2*)&g_xl[i] = make_uint2(packh2(l0, l1), packh2(l2, l3));
    } else {
        const int w = blockIdx.x - 8192;
        const int z = w >> 10;
        const int b2 = w & 1023;
        const int n0 = (b2 & 31) * 32;
        const int k0 = (b2 >> 5) * 32;
        const float* W = (z == 0) ? Wq : (z == 1) ? Wk : (z == 2) ? Wv : Wo;
        const int tx = threadIdx.x & 31, ty = threadIdx.x >> 5;   // 32 x 8
        #pragma unroll
        for (int i = 0; i < 4; ++i)
            t[ty + i * 8][tx] = W[(size_t)(k0 + ty + i * 8) * DOUT + n0 + tx];
        __syncthreads();
        __half* wh = g_wth + (size_t)z * DIN * DOUT;
        __half* wl = g_wtl + (size_t)z * DIN * DOUT;
        #pragma unroll
        for (int i = 0; i < 4; ++i) {
            int n = n0 + ty + i * 8, k = k0 + tx;
            float v = t[tx][ty + i * 8];                 // = W[k][n]
            __half h = __float2half_rn(v);
            wh[(size_t)n * DIN + k] = h;
            wl[(size_t)n * DIN + k] = __float2half_rn(v - __half2float(h));
        }
    }
}

// ---------------------------------------------------------------------------
// fp16 hi/lo split GEMM via mma.sync.  CTA 64x128, 128 threads (warp 32x64),
// KC=32, 2 stages, 3 CTAs/SM.
// Passes: ah*bh + al*bh always (A correction); ah*bl only on the score path
// (MODE 0, bz<2).  Value path (V gemm, out-proj) = 2-pass.
// MODE 0: A = x, B = W^T[z] -> Q/K fp16 hi/lo, V fp16 (Q pre-scaled).
// MODE 1: A = ctx limbs, B = Wo^T hi, +bias -> d_out fp32.
// ---------------------------------------------------------------------------
#define KC     32
#define PITCH  80
#define ATILE  (64 * PITCH)              // 5120
#define BTILE  (128 * PITCH)             // 10240
#define STAGEB (2 * ATILE + 2 * BTILE)   // 30720 (Ah, Al, Bh, Bl)
#define GSMEM  (2 * STAGEB)              // 61440 -> 3 CTAs/SM

template<int MODE>
__global__ __launch_bounds__(128, 3) void mma_gemm(const float* __restrict__ bias,
                                                   float* __restrict__ dout)
{
    extern __shared__ char smc[];
    const uint32_t smb = smem_u32(smc);

    const int tid  = threadIdx.x;
    const int lane = tid & 31;
    const int wid  = tid >> 5;
    const int wm   = (wid & 1) * 32;
    const int wn   = (wid >> 1) * 64;

    const int m0 = blockIdx.x * 64;
    const int n0 = blockIdx.y * 128;
    const int bz = (MODE == 0) ? blockIdx.z : 3;
    const bool full3 = (MODE == 0) && (bz < 2);      // Q,K gemms keep W correction

    const __half* Ah = (MODE == 0) ? g_xh : g_cxh;
    const __half* Al = (MODE == 0) ? g_xl : g_cxl;
    const __half* Bh = g_wth + (size_t)bz * DIN * DOUT;
    const __half* Bl = g_wtl + (size_t)bz * DIN * DOUT;

    const char* agh = (const char*)Ah + ((size_t)m0 * DIN) * 2;
    const char* agl = (const char*)Al + ((size_t)m0 * DIN) * 2;
    const char* bgh = (const char*)Bh + ((size_t)n0 * DIN) * 2;
    const char* bgl = (const char*)Bl + ((size_t)n0 * DIN) * 2;

    auto load = [&](int c, int st) {
        const uint32_t base = smb + st * STAGEB;
        const size_t cko = (size_t)c * KC * 2;
        #pragma unroll
        for (int i = 0; i < 2; ++i) {
            int s   = tid + i * 128;
            int r   = s >> 2;
            int seg = s & 3;
            size_t  go  = (size_t)r * (DIN * 2) + cko + seg * 16;
            uint32_t dof = r * PITCH + seg * 16;
            cp16(base + dof,         agh + go);
            cp16(base + ATILE + dof, agl + go);
        }
        #pragma unroll
        for (int i = 0; i < 4; ++i) {
            int s   = tid + i * 128;
            int r   = s >> 2;
            int seg = s & 3;
            size_t  go  = (size_t)r * (DIN * 2) + cko + seg * 16;
            uint32_t dof = r * PITCH + seg * 16;
            cp16(base + 2 * ATILE + dof, bgh + go);
            if (full3) cp16(base + 2 * ATILE + BTILE + dof, bgl + go);
        }
    };

    float C[2][8][4] = {};

    const uint32_t aRow = wm + (lane & 15);
    const uint32_t aCol = (lane >> 4) * 16;
    const uint32_t bRow = wn + ((lane >> 4) << 3) + (lane & 7);
    const uint32_t bCol = ((lane >> 3) & 1) * 16;

    load(0, 0);
    cp_commit();

    for (int c = 0; c < DIN / KC; ++c) {
        const int st = c & 1;
        if (c + 1 < DIN / KC) { load(c + 1, st ^ 1); cp_commit(); cp_wait1(); }
        else                  { cp_wait0(); }
        __syncthreads();

        const uint32_t sA = smb + st * STAGEB;
        const uint32_t sB = sA + 2 * ATILE;

        #pragma unroll
        for (int ks = 0; ks < 2; ++ks) {
            uint32_t ah[2][4], al[2][4], bh[8][2];
            #pragma unroll
            for (int i = 0; i < 2; ++i) {
                uint32_t ad = sA + (aRow + i * 16) * PITCH + ks * 32 + aCol;
                ldsm4(ah[i][0], ah[i][1], ah[i][2], ah[i][3], ad);
                ldsm4(al[i][0], al[i][1], al[i][2], al[i][3], ad + ATILE);
            }
            #pragma unroll
            for (int p = 0; p < 4; ++p) {
                uint32_t bd = sB + (bRow + p * 16) * PITCH + ks * 32 + bCol;
                ldsm4(bh[2*p][0], bh[2*p][1], bh[2*p+1][0], bh[2*p+1][1], bd);
            }
            #pragma unroll
            for (int i = 0; i < 2; ++i)
                #pragma unroll
                for (int j = 0; j < 8; ++j)
                    mma16816(C[i][j], ah[i], bh[j]);
            #pragma unroll
            for (int i = 0; i < 2; ++i)
                #pragma unroll
                for (int j = 0; j < 8; ++j)
                    mma16816(C[i][j], al[i], bh[j]);
            if (full3) {
                uint32_t bl[8][2];
                #pragma unroll
                for (int p = 0; p < 4; ++p) {
                    uint32_t bd = sB + BTILE + (bRow + p * 16) * PITCH + ks * 32 + bCol;
                    ldsm4(bl[2*p][0], bl[2*p][1], bl[2*p+1][0], bl[2*p+1][1], bd);
                }
                #pragma unroll
                for (int i = 0; i < 2; ++i)
                    #pragma unroll
                    for (int j = 0; j < 8; ++j)
                        mma16816(C[i][j], ah[i], bl[j]);
            }
        }
        __syncthreads();
    }

    // ---- epilogue ----
    const int rr = lane >> 2;
    const int cc = (lane & 3) * 2;
    const float scl = (MODE == 0 && bz == 0) ? 0.1803368801111244f : 1.0f; // (1/8)*log2(e)
    #pragma unroll
    for (int i = 0; i < 2; ++i) {
        #pragma unroll
        for (int j = 0; j < 8; ++j) {
            int m1 = m0 + wm + i * 16 + rr;
            int m2 = m1 + 8;
            int n  = n0 + wn + j * 8 + cc;
            if (MODE == 0) {
                __half* oh = (bz == 0) ? g_qh : (bz == 1) ? g_kh : g_vh;
                __half* ol = (bz == 0) ? g_ql : g_kl;
                int head = n >> 6, hd = n & 63;
                #pragma unroll
                for (int half = 0; half < 2; ++half) {
                    int mm = half ? m2 : m1;
                    float v0 = C[i][j][half * 2] * scl, v1 = C[i][j][half * 2 + 1] * scl;
                    __half h0 = __float2half_rn(v0), h1 = __float2half_rn(v1);
                    int b = mm >> 11, s = mm & 2047;
                    size_t idx = (((size_t)(b * HH + head) * SS + s) * HD) + hd;
                    *(uint32_t*)&oh[idx] = packh2h(h0, h1);
                    if (bz < 2)
                        *(uint32_t*)&ol[idx] = packh2(v0 - __half2float(h0),
                                                      v1 - __half2float(h1));
                }
            } else {
                float b0 = bias[n], b1 = bias[n + 1];
                *(float2*)&dout[(size_t)m1 * DOUT + n] = make_float2(C[i][j][0] + b0, C[i][j][1] + b1);
                *(float2*)&dout[(size_t)m2 * DOUT + n] = make_float2(C[i][j][2] + b0, C[i][j][3] + b1);
            }
        }
    }
}

// ---------------------------------------------------------------------------
// Causal flash attention (fp16, max-free softmax, ex2.approx).
// S = 3-pass (Qh*Kh + Ql*Kh + Qh*Kl);  PV = 2-pass (Ph*Vh + Pl*Vh).
// CTA: 64 queries x (b,h), 128 threads.  KV tiles of 32 (Kh,Kl,Vh), 3 CTAs/SM.
// ---------------------------------------------------------------------------
#define APITCH  144
#define QBYTES  (64 * APITCH)
#define KVB     (32 * APITCH)
#define OFF_ST  (2 * QBYTES)
#define STG_B   (3 * KVB)               // Kh, Kl, Vh
#define ATTN_SMEM (OFF_ST + 2 * STG_B)  // 46080

__global__ __launch_bounds__(128, 3) void attn_mma_kernel()
{
    extern __shared__ char smc[];
    const uint32_t smb = smem_u32(smc);

    const int tid  = threadIdx.x;
    const int lane = tid & 31;
    const int wid  = tid >> 5;
    const int qt   = (int)(gridDim.x - 1) - (int)blockIdx.x;  // heavy tiles first
    const int h    = blockIdx.y, b = blockIdx.z;
    const int wq   = wid * 16;

    const size_t bh = ((size_t)(b * HH + h)) * SS;
    const char* gqh = (const char*)(g_qh + (bh + (size_t)qt * 64) * HD);
    const char* gql = (const char*)(g_ql + (bh + (size_t)qt * 64) * HD);
    const char* gkh = (const char*)(g_kh + bh * HD);
    const char* gkl = (const char*)(g_kl + bh * HD);
    const char* gvh = (const char*)(g_vh + bh * HD);

    #pragma unroll
    for (int i = 0; i < 4; ++i) {
        int s = tid + i * 128;
        int r = s >> 3, seg = s & 7;
        uint32_t doff = r * APITCH + seg * 16;
        size_t   goff = (size_t)r * 128 + seg * 16;
        cp16(smb + doff,          gqh + goff);
        cp16(smb + QBYTES + doff, gql + goff);
    }
    auto loadKV = [&](int jt, int st) {
        const uint32_t base = smb + OFF_ST + st * STG_B;
        const size_t g0 = (size_t)jt * 32 * 128;
        #pragma unroll
        for (int i = 0; i < 2; ++i) {
            int s = tid + i * 128;
            int r = s >> 3, seg = s & 7;
            uint32_t doff = r * APITCH + seg * 16;
            size_t   goff = g0 + (size_t)r * 128 + seg * 16;
            cp16(base + doff,           gkh + goff);
            cp16(base + KVB + doff,     gkl + goff);
            cp16(base + 2 * KVB + doff, gvh + goff);
        }
    };
    loadKV(0, 0);
    cp_commit();

    uint32_t qh[4][4], ql[4][4];
    float O[8][4] = {};
    float rs0 = 0.f, rs1 = 0.f;

    const uint32_t aoff = (wq + (lane & 15)) * APITCH + (lane >> 4) * 16;
    const uint32_t krow = (((lane >> 4) << 3) + (lane & 7)) * APITCH + ((lane >> 3) & 1) * 16;
    const uint32_t vrow = (lane & 15) * APITCH + (lane >> 4) * 16;

    const int jmax = 2 * qt + 1;
    for (int jt = 0; jt <= jmax; ++jt) {
        const int st = jt & 1;
        if (jt < jmax) { loadKV(jt + 1, st ^ 1); cp_commit(); cp_wait1(); }
        else           { cp_wait0(); }
        __syncthreads();

        if (jt == 0) {
            #pragma unroll
            for (int f = 0; f < 4; ++f) {
                ldsm4(qh[f][0], qh[f][1], qh[f][2], qh[f][3], smb + aoff + f * 32);
                ldsm4(ql[f][0], ql[f][1], ql[f][2], ql[f][3], smb + QBYTES + aoff + f * 32);
            }
        }

        const bool active = !(jt == jmax && wq < 32);
        if (active) {
            const uint32_t kb = smb + OFF_ST + st * STG_B;

            // ---- S = Q K^T (3-pass fp16 split) ----
            float s_[4][4] = {};
            #pragma unroll
            for (int f = 0; f < 4; ++f) {
                uint32_t kh[2][4], kl[2][4];
                #pragma unroll
                for (int jp = 0; jp < 2; ++jp) {
                    uint32_t a = kb + krow + jp * 16 * APITCH + f * 32;
                    ldsm4(kh[jp][0], kh[jp][1], kh[jp][2], kh[jp][3], a);
                    ldsm4(kl[jp][0], kl[jp][1], kl[jp][2], kl[jp][3], a + KVB);
                }
                #pragma unroll
                for (int jp = 0; jp < 2; ++jp) {
                    mma16816(s_[2*jp],     qh[f], kh[jp]);
                    mma16816(s_[2*jp + 1], qh[f], kh[jp] + 2);
                }
                #pragma unroll
                for (int jp = 0; jp < 2; ++jp) {
                    mma16816(s_[2*jp],     ql[f], kh[jp]);
                    mma16816(s_[2*jp + 1], ql[f], kh[jp] + 2);
                }
                #pragma unroll
                for (int jp = 0; jp < 2; ++jp) {
                    mma16816(s_[2*jp],     qh[f], kl[jp]);
                    mma16816(s_[2*jp + 1], qh[f], kl[jp] + 2);
                }
            }

            if (jt >= 2 * qt) {
                const int qrow  = qt * 64 + wq + (lane >> 2);
                const int kcol0 = jt * 32 + (lane & 3) * 2;
                #pragma unroll
                for (int j = 0; j < 4; ++j) {
                    int c0 = kcol0 + j * 8, c1 = c0 + 1;
                    if (c0 > qrow)     s_[j][0] = -1e30f;
                    if (c1 > qrow)     s_[j][1] = -1e30f;
                    if (c0 > qrow + 8) s_[j][2] = -1e30f;
                    if (c1 > qrow + 8) s_[j][3] = -1e30f;
                }
            }

            // ---- max-free softmax (MUFU.EX2) ----
            #pragma unroll
            for (int j = 0; j < 4; ++j) {
                s_[j][0] = ex2(s_[j][0]);
                s_[j][1] = ex2(s_[j][1]);
                s_[j][2] = ex2(s_[j][2]);
                s_[j][3] = ex2(s_[j][3]);
                rs0 += s_[j][0] + s_[j][1];
                rs1 += s_[j][2] + s_[j][3];
            }

            // ---- O += P V (2-pass: Ph*Vh + Pl*Vh) ----
            const uint32_t vb = kb + 2 * KVB + vrow;
            #pragma unroll
            for (int f = 0; f < 2; ++f) {
                uint32_t ph[4], pl[4];
                #pragma unroll
                for (int t = 0; t < 2; ++t) {
                    float p0 = s_[2*f + t][0], p1 = s_[2*f + t][1];
                    float p2 = s_[2*f + t][2], p3 = s_[2*f + t][3];
                    __half h0 = __float2half_rn(p0), h1 = __float2half_rn(p1);
                    __half h2 = __float2half_rn(p2), h3 = __float2half_rn(p3);
                    ph[2*t]   = packh2h(h0, h1);
                    ph[2*t+1] = packh2h(h2, h3);
                    pl[2*t]   = packh2(p0 - __half2float(h0), p1 - __half2float(h1));
                    pl[2*t+1] = packh2(p2 - __half2float(h2), p3 - __half2float(h3));
                }
                const uint32_t va = vb + f * 16 * APITCH;
                uint32_t vh[4][4];
                #pragma unroll
                for (int dj = 0; dj < 4; ++dj)
                    ldsm4t(vh[dj][0], vh[dj][1], vh[dj][2], vh[dj][3], va + dj * 32);
                #pragma unroll
                for (int dj = 0; dj < 4; ++dj) {
                    mma16816(O[2*dj],     ph, vh[dj]);
                    mma16816(O[2*dj + 1], ph, vh[dj] + 2);
                }
                #pragma unroll
                for (int dj = 0; dj < 4; ++dj) {
                    mma16816(O[2*dj],     pl, vh[dj]);
                    mma16816(O[2*dj + 1], pl, vh[dj] + 2);
                }
            }
        }
        __syncthreads();
    }

    // ---- finalize ----
    rs0 += __shfl_xor_sync(0xffffffffu, rs0, 1);
    rs0 += __shfl_xor_sync(0xffffffffu, rs0, 2);
    rs1 += __shfl_xor_sync(0xffffffffu, rs1, 1);
    rs1 += __shfl_xor_sync(0xffffffffu, rs1, 2);
    const float inv0 = 1.0f / rs0, inv1 = 1.0f / rs1;

    const int r    = lane >> 2;
    const int dcol = (lane & 3) * 2;
    const int row0 = qt * 64 + wq + r;
    const size_t base0 = ((size_t)b * SS + row0) * DOUT + h * 64;
    const size_t base1 = base0 + (size_t)8 * DOUT;
    #pragma unroll
    for (int dj = 0; dj < 8; ++dj) {
        int d = dj * 8 + dcol;
        {
            float v0 = O[dj][0] * inv0, v1 = O[dj][1] * inv0;
            __half h0 = __float2half_rn(v0), h1 = __float2half_rn(v1);
            *(uint32_t*)&g_cxh[base0 + d] = packh2h(h0, h1);
            *(uint32_t*)&g_cxl[base0 + d] = packh2(v0 - __half2float(h0),
                                                   v1 - __half2float(h1));
        }
        {
            float v2 = O[dj][2] * inv1, v3 = O[dj][3] * inv1;
            __half h2 = __float2half_rn(v2), h3 = __float2half_rn(v3);
            *(uint32_t*)&g_cxh[base1 + d] = packh2h(h2, h3);
            *(uint32_t*)&g_cxl[base1 + d] = packh2(v2 - __half2float(h2),
                                                   v3 - __half2float(h3));
        }
    }
}

// ---------------------------------------------------------------------------
extern "C" void kernel_launch(void* const* d_in, const int* in_sizes, int n_in,
                              void* d_out, int out_size)
{
    const float* x  = (const float*)d_in[0];
    const float* Wq = (const float*)d_in[1];
    const float* Wk = (const float*)d_in[2];
    const float* Wv = (const float*)d_in[3];
    const float* Wo = (const float*)d_in[4];
    const float* bo = (const float*)d_in[5];
    float* out = (float*)d_out;

    cudaFuncSetAttribute(mma_gemm<0>, cudaFuncAttributeMaxDynamicSharedMemorySize, GSMEM);
    cudaFuncSetAttribute(mma_gemm<1>, cudaFuncAttributeMaxDynamicSharedMemorySize, GSMEM);
    cudaFuncSetAttribute(attn_mma_kernel, cudaFuncAttributeMaxDynamicSharedMemorySize, ATTN_SMEM);

    conv_all_kernel<<<12288, 256>>>(x, Wq, Wk, Wv, Wo);
    mma_gemm<0><<<dim3(128, 8, 3), 128, GSMEM>>>(nullptr, nullptr);
    attn_mma_kernel<<<dim3(32, HH, BB), 128, ATTN_SMEM>>>();
    mma_gemm<1><<<dim3(128, 8), 128, GSMEM>>>(bo, out);
}

// round 15
// speedup vs baseline: 2.0620x; 1.5432x over previous
#include <cuda_runtime.h>
#include <cuda_fp16.h>
#include <cstdint>

#define BB   4
#define HH   16
#define SS   2048
#define HD   64
#define DIN  1024
#define DOUT 1024

// ---------------------------------------------------------------------------
// Scratch (__device__ globals; no allocations allowed).
// Q/K/V single fp16; ctx keeps hi/lo limbs for the 2-pass out-projection.
// ---------------------------------------------------------------------------
__device__ __half g_xh[BB * SS * DIN];       // x fp16
__device__ __half g_wth[4 * DIN * DOUT];     // W^T fp16 [n][k], 4 mats
__device__ __half g_qh[BB * HH * SS * HD];   // Q (pre-scaled) [B,H,S,HD]
__device__ __half g_kh[BB * HH * SS * HD];
__device__ __half g_vh[BB * HH * SS * HD];
__device__ __half g_cxh[BB * SS * DOUT];     // ctx hi/lo [8192][1024]
__device__ __half g_cxl[BB * SS * DOUT];

// ---------------------------------------------------------------------------
// Helpers
// ---------------------------------------------------------------------------
__device__ __forceinline__ uint32_t smem_u32(const void* p) {
    uint32_t a;
    asm("{ .reg .u64 t; cvta.to.shared.u64 t, %1; cvt.u32.u64 %0, t; }" : "=r"(a) : "l"(p));
    return a;
}
__device__ __forceinline__ float ex2(float x) {
    float y;
    asm("ex2.approx.f32 %0, %1;" : "=f"(y) : "f"(x));
    return y;
}
__device__ __forceinline__ uint32_t packh2(float a, float b) {
    __half2 t = __floats2half2_rn(a, b);
    return *(uint32_t*)&t;
}
__device__ __forceinline__ uint32_t packh2h(__half a, __half b) {
    __half2 t = __halves2half2(a, b);
    return *(uint32_t*)&t;
}
__device__ __forceinline__ void ldsm4(uint32_t& r0, uint32_t& r1, uint32_t& r2, uint32_t& r3,
                                      uint32_t addr) {
    asm volatile("ldmatrix.sync.aligned.m8n8.x4.shared.b16 {%0,%1,%2,%3}, [%4];"
                 : "=r"(r0), "=r"(r1), "=r"(r2), "=r"(r3) : "r"(addr));
}
__device__ __forceinline__ void ldsm4t(uint32_t& r0, uint32_t& r1, uint32_t& r2, uint32_t& r3,
                                       uint32_t addr) {
    asm volatile("ldmatrix.sync.aligned.m8n8.x4.trans.shared.b16 {%0,%1,%2,%3}, [%4];"
                 : "=r"(r0), "=r"(r1), "=r"(r2), "=r"(r3) : "r"(addr));
}
__device__ __forceinline__ void mma16816(float* c, const uint32_t* a, const uint32_t* b) {
    asm volatile(
        "mma.sync.aligned.m16n8k16.row.col.f32.f16.f16.f32 "
        "{%0,%1,%2,%3}, {%4,%5,%6,%7}, {%8,%9}, {%0,%1,%2,%3};"
        : "+f"(c[0]), "+f"(c[1]), "+f"(c[2]), "+f"(c[3])
        : "r"(a[0]), "r"(a[1]), "r"(a[2]), "r"(a[3]), "r"(b[0]), "r"(b[1]));
}
__device__ __forceinline__ void cp16(uint32_t dst, const void* src) {
    asm volatile("cp.async.cg.shared.global [%0], [%1], 16;" :: "r"(dst), "l"(src));
}
__device__ __forceinline__ void cp_commit() { asm volatile("cp.async.commit_group;" ::: "memory"); }
__device__ __forceinline__ void cp_wait1()  { asm volatile("cp.async.wait_group 1;" ::: "memory"); }
__device__ __forceinline__ void cp_wait0()  { asm volatile("cp.async.wait_group 0;" ::: "memory"); }

// ---------------------------------------------------------------------------
// Merged conversion: blocks [0, 8192) convert x -> fp16; [8192, 12288) W^T -> fp16.
// ---------------------------------------------------------------------------
__global__ __launch_bounds__(256) void conv_all_kernel(
    const float* __restrict__ x,
    const float* __restrict__ Wq, const float* __restrict__ Wk,
    const float* __restrict__ Wv, const float* __restrict__ Wo)
{
    __shared__ float t[32][33];
    if (blockIdx.x < 8192) {
        int i = (blockIdx.x * 256 + threadIdx.x) * 4;
        float4 v = *(const float4*)(x + i);
        *(uint2*)&g_xh[i] = make_uint2(packh2(v.x, v.y), packh2(v.z, v.w));
    } else {
        const int w = blockIdx.x - 8192;
        const int z = w >> 10;
        const int b2 = w & 1023;
        const int n0 = (b2 & 31) * 32;
        const int k0 = (b2 >> 5) * 32;
        const float* W = (z == 0) ? Wq : (z == 1) ? Wk : (z == 2) ? Wv : Wo;
        const int tx = threadIdx.x & 31, ty = threadIdx.x >> 5;   // 32 x 8
        #pragma unroll
        for (int i = 0; i < 4; ++i)
            t[ty + i * 8][tx] = W[(size_t)(k0 + ty + i * 8) * DOUT + n0 + tx];
        __syncthreads();
        __half* wh = g_wth + (size_t)z * DIN * DOUT;
        #pragma unroll
        for (int i = 0; i < 4; ++i) {
            int n = n0 + ty + i * 8, k = k0 + tx;
            wh[(size_t)n * DIN + k] = __float2half_rn(t[tx][ty + i * 8]);
        }
    }
}

// ---------------------------------------------------------------------------
// fp16 GEMM via mma.sync.  CTA 64x128, 128 threads (warp 32x64), KC=32,
// 2 stages, 3 CTAs/SM.
// MODE 0: 1-pass, A = x fp16, B = W^T[z] -> Q/K/V fp16 (Q pre-scaled).
// MODE 1: 2-pass (ctx hi + ctx lo), B = Wo^T, +bias -> d_out fp32.
// ---------------------------------------------------------------------------
#define KC     32
#define PITCH  80
#define ATILE  (64 * PITCH)              // 5120
#define BTILE  (128 * PITCH)             // 10240
#define STAGEB (2 * ATILE + BTILE)       // 20480 (Ah, Al, Bh)
#define GSMEM  (2 * STAGEB)              // 40960

template<int MODE>
__global__ __launch_bounds__(128, 3) void mma_gemm(const float* __restrict__ bias,
                                                   float* __restrict__ dout)
{
    extern __shared__ char smc[];
    const uint32_t smb = smem_u32(smc);

    const int tid  = threadIdx.x;
    const int lane = tid & 31;
    const int wid  = tid >> 5;
    const int wm   = (wid & 1) * 32;
    const int wn   = (wid >> 1) * 64;

    const int m0 = blockIdx.x * 64;
    const int n0 = blockIdx.y * 128;
    const int bz = (MODE == 0) ? blockIdx.z : 3;

    const __half* Ah = (MODE == 0) ? g_xh : g_cxh;
    const __half* Bh = g_wth + (size_t)bz * DIN * DOUT;

    const char* agh = (const char*)Ah + ((size_t)m0 * DIN) * 2;
    const char* agl = (const char*)g_cxl + ((size_t)m0 * DIN) * 2;   // MODE 1 only
    const char* bgh = (const char*)Bh + ((size_t)n0 * DIN) * 2;

    auto load = [&](int c, int st) {
        const uint32_t base = smb + st * STAGEB;
        const size_t cko = (size_t)c * KC * 2;
        #pragma unroll
        for (int i = 0; i < 2; ++i) {
            int s   = tid + i * 128;
            int r   = s >> 2;
            int seg = s & 3;
            size_t  go  = (size_t)r * (DIN * 2) + cko + seg * 16;
            uint32_t dof = r * PITCH + seg * 16;
            cp16(base + dof, agh + go);
            if (MODE == 1) cp16(base + ATILE + dof, agl + go);
        }
        #pragma unroll
        for (int i = 0; i < 4; ++i) {
            int s   = tid + i * 128;
            int r   = s >> 2;
            int seg = s & 3;
            size_t  go  = (size_t)r * (DIN * 2) + cko + seg * 16;
            uint32_t dof = r * PITCH + seg * 16;
            cp16(base + 2 * ATILE + dof, bgh + go);
        }
    };

    float C[2][8][4] = {};

    const uint32_t aRow = wm + (lane & 15);
    const uint32_t aCol = (lane >> 4) * 16;
    const uint32_t bRow = wn + ((lane >> 4) << 3) + (lane & 7);
    const uint32_t bCol = ((lane >> 3) & 1) * 16;

    load(0, 0);
    cp_commit();

    for (int c = 0; c < DIN / KC; ++c) {
        const int st = c & 1;
        if (c + 1 < DIN / KC) { load(c + 1, st ^ 1); cp_commit(); cp_wait1(); }
        else                  { cp_wait0(); }
        __syncthreads();

        const uint32_t sA = smb + st * STAGEB;
        const uint32_t sB = sA + 2 * ATILE;

        #pragma unroll
        for (int ks = 0; ks < 2; ++ks) {
            uint32_t ah[2][4], bh[8][2];
            #pragma unroll
            for (int i = 0; i < 2; ++i) {
                uint32_t ad = sA + (aRow + i * 16) * PITCH + ks * 32 + aCol;
                ldsm4(ah[i][0], ah[i][1], ah[i][2], ah[i][3], ad);
            }
            #pragma unroll
            for (int p = 0; p < 4; ++p) {
                uint32_t bd = sB + (bRow + p * 16) * PITCH + ks * 32 + bCol;
                ldsm4(bh[2*p][0], bh[2*p][1], bh[2*p+1][0], bh[2*p+1][1], bd);
            }
            #pragma unroll
            for (int i = 0; i < 2; ++i)
                #pragma unroll
                for (int j = 0; j < 8; ++j)
                    mma16816(C[i][j], ah[i], bh[j]);
            if (MODE == 1) {
                uint32_t al[2][4];
                #pragma unroll
                for (int i = 0; i < 2; ++i) {
                    uint32_t ad = sA + ATILE + (aRow + i * 16) * PITCH + ks * 32 + aCol;
                    ldsm4(al[i][0], al[i][1], al[i][2], al[i][3], ad);
                }
                #pragma unroll
                for (int i = 0; i < 2; ++i)
                    #pragma unroll
                    for (int j = 0; j < 8; ++j)
                        mma16816(C[i][j], al[i], bh[j]);
            }
        }
        __syncthreads();
    }

    // ---- epilogue ----
    const int rr = lane >> 2;
    const int cc = (lane & 3) * 2;
    const float scl = (MODE == 0 && bz == 0) ? 0.1803368801111244f : 1.0f; // (1/8)*log2(e)
    #pragma unroll
    for (int i = 0; i < 2; ++i) {
        #pragma unroll
        for (int j = 0; j < 8; ++j) {
            int m1 = m0 + wm + i * 16 + rr;
            int m2 = m1 + 8;
            int n  = n0 + wn + j * 8 + cc;
            if (MODE == 0) {
                __half* oh = (bz == 0) ? g_qh : (bz == 1) ? g_kh : g_vh;
                int head = n >> 6, hd = n & 63;
                #pragma unroll
                for (int half = 0; half < 2; ++half) {
                    int mm = half ? m2 : m1;
                    int b = mm >> 11, s = mm & 2047;
                    size_t idx = (((size_t)(b * HH + head) * SS + s) * HD) + hd;
                    *(uint32_t*)&oh[idx] = packh2(C[i][j][half * 2] * scl,
                                                  C[i][j][half * 2 + 1] * scl);
                }
            } else {
                float b0 = bias[n], b1 = bias[n + 1];
                *(float2*)&dout[(size_t)m1 * DOUT + n] = make_float2(C[i][j][0] + b0, C[i][j][1] + b1);
                *(float2*)&dout[(size_t)m2 * DOUT + n] = make_float2(C[i][j][2] + b0, C[i][j][3] + b1);
            }
        }
    }
}

// ---------------------------------------------------------------------------
// Causal flash attention (fp16, max-free softmax, ex2.approx).
// S = 1-pass (Qh*Kh);  PV = 2-pass (Ph*Vh + Pl*Vh).
// CTA: 64 queries x (b,h), 128 threads.  KV tiles of 32 (Kh, Vh), 3 CTAs/SM.
// ---------------------------------------------------------------------------
#define APITCH  144
#define QBYTES  (64 * APITCH)           // 9216
#define KVB     (32 * APITCH)           // 4608
#define OFF_ST  QBYTES
#define STG_B   (2 * KVB)               // 9216 (Kh, Vh)
#define ATTN_SMEM (OFF_ST + 2 * STG_B)  // 27648

__global__ __launch_bounds__(128, 3) void attn_mma_kernel()
{
    extern __shared__ char smc[];
    const uint32_t smb = smem_u32(smc);

    const int tid  = threadIdx.x;
    const int lane = tid & 31;
    const int wid  = tid >> 5;
    const int qt   = (int)(gridDim.x - 1) - (int)blockIdx.x;  // heavy tiles first
    const int h    = blockIdx.y, b = blockIdx.z;
    const int wq   = wid * 16;

    const size_t bh = ((size_t)(b * HH + h)) * SS;
    const char* gqh = (const char*)(g_qh + (bh + (size_t)qt * 64) * HD);
    const char* gkh = (const char*)(g_kh + bh * HD);
    const char* gvh = (const char*)(g_vh + bh * HD);

    #pragma unroll
    for (int i = 0; i < 4; ++i) {
        int s = tid + i * 128;
        int r = s >> 3, seg = s & 7;
        cp16(smb + r * APITCH + seg * 16, gqh + (size_t)r * 128 + seg * 16);
    }
    auto loadKV = [&](int jt, int st) {
        const uint32_t base = smb + OFF_ST + st * STG_B;
        const size_t g0 = (size_t)jt * 32 * 128;
        #pragma unroll
        for (int i = 0; i < 2; ++i) {
            int s = tid + i * 128;
            int r = s >> 3, seg = s & 7;
            uint32_t doff = r * APITCH + seg * 16;
            size_t   goff = g0 + (size_t)r * 128 + seg * 16;
            cp16(base + doff,       gkh + goff);
            cp16(base + KVB + doff, gvh + goff);
        }
    };
    loadKV(0, 0);
    cp_commit();

    uint32_t qh[4][4];
    float O[8][4] = {};
    float rs0 = 0.f, rs1 = 0.f;

    const uint32_t aoff = (wq + (lane & 15)) * APITCH + (lane >> 4) * 16;
    const uint32_t krow = (((lane >> 4) << 3) + (lane & 7)) * APITCH + ((lane >> 3) & 1) * 16;
    const uint32_t vrow = (lane & 15) * APITCH + (lane >> 4) * 16;

    const int jmax = 2 * qt + 1;
    for (int jt = 0; jt <= jmax; ++jt) {
        const int st = jt & 1;
        if (jt < jmax) { loadKV(jt + 1, st ^ 1); cp_commit(); cp_wait1(); }
        else           { cp_wait0(); }
        __syncthreads();

        if (jt == 0) {
            #pragma unroll
            for (int f = 0; f < 4; ++f)
                ldsm4(qh[f][0], qh[f][1], qh[f][2], qh[f][3], smb + aoff + f * 32);
        }

        const bool active = !(jt == jmax && wq < 32);
        if (active) {
            const uint32_t kb = smb + OFF_ST + st * STG_B;

            // ---- S = Q K^T (1-pass fp16) ----
            float s_[4][4] = {};
            #pragma unroll
            for (int f = 0; f < 4; ++f) {
                uint32_t kh[2][4];
                #pragma unroll
                for (int jp = 0; jp < 2; ++jp) {
                    uint32_t a = kb + krow + jp * 16 * APITCH + f * 32;
                    ldsm4(kh[jp][0], kh[jp][1], kh[jp][2], kh[jp][3], a);
                }
                #pragma unroll
                for (int jp = 0; jp < 2; ++jp) {
                    mma16816(s_[2*jp],     qh[f], kh[jp]);
                    mma16816(s_[2*jp + 1], qh[f], kh[jp] + 2);
                }
            }

            if (jt >= 2 * qt) {
                const int qrow  = qt * 64 + wq + (lane >> 2);
                const int kcol0 = jt * 32 + (lane & 3) * 2;
                #pragma unroll
                for (int j = 0; j < 4; ++j) {
                    int c0 = kcol0 + j * 8, c1 = c0 + 1;
                    if (c0 > qrow)     s_[j][0] = -1e30f;
                    if (c1 > qrow)     s_[j][1] = -1e30f;
                    if (c0 > qrow + 8) s_[j][2] = -1e30f;
                    if (c1 > qrow + 8) s_[j][3] = -1e30f;
                }
            }

            // ---- max-free softmax (MUFU.EX2) ----
            #pragma unroll
            for (int j = 0; j < 4; ++j) {
                s_[j][0] = ex2(s_[j][0]);
                s_[j][1] = ex2(s_[j][1]);
                s_[j][2] = ex2(s_[j][2]);
                s_[j][3] = ex2(s_[j][3]);
                rs0 += s_[j][0] + s_[j][1];
                rs1 += s_[j][2] + s_[j][3];
            }

            // ---- O += P V (2-pass: Ph*Vh + Pl*Vh) ----
            const uint32_t vb = kb + KVB + vrow;
            #pragma unroll
            for (int f = 0; f < 2; ++f) {
                uint32_t ph[4], pl[4];
                #pragma unroll
                for (int t = 0; t < 2; ++t) {
                    float p0 = s_[2*f + t][0], p1 = s_[2*f + t][1];
                    float p2 = s_[2*f + t][2], p3 = s_[2*f + t][3];
                    __half h0 = __float2half_rn(p0), h1 = __float2half_rn(p1);
                    __half h2 = __float2half_rn(p2), h3 = __float2half_rn(p3);
                    ph[2*t]   = packh2h(h0, h1);
                    ph[2*t+1] = packh2h(h2, h3);
                    pl[2*t]   = packh2(p0 - __half2float(h0), p1 - __half2float(h1));
                    pl[2*t+1] = packh2(p2 - __half2float(h2), p3 - __half2float(h3));
                }
                const uint32_t va = vb + f * 16 * APITCH;
                uint32_t vh[4][4];
                #pragma unroll
                for (int dj = 0; dj < 4; ++dj)
                    ldsm4t(vh[dj][0], vh[dj][1], vh[dj][2], vh[dj][3], va + dj * 32);
                #pragma unroll
                for (int dj = 0; dj < 4; ++dj) {
                    mma16816(O[2*dj],     ph, vh[dj]);
                    mma16816(O[2*dj + 1], ph, vh[dj] + 2);
                }
                #pragma unroll
                for (int dj = 0; dj < 4; ++dj) {
                    mma16816(O[2*dj],     pl, vh[dj]);
                    mma16816(O[2*dj + 1], pl, vh[dj] + 2);
                }
            }
        }
        __syncthreads();
    }

    // ---- finalize ----
    rs0 += __shfl_xor_sync(0xffffffffu, rs0, 1);
    rs0 += __shfl_xor_sync(0xffffffffu, rs0, 2);
    rs1 += __shfl_xor_sync(0xffffffffu, rs1, 1);
    rs1 += __shfl_xor_sync(0xffffffffu, rs1, 2);
    const float inv0 = 1.0f / rs0, inv1 = 1.0f / rs1;

    const int r    = lane >> 2;
    const int dcol = (lane & 3) * 2;
    const int row0 = qt * 64 + wq + r;
    const size_t base0 = ((size_t)b * SS + row0) * DOUT + h * 64;
    const size_t base1 = base0 + (size_t)8 * DOUT;
    #pragma unroll
    for (int dj = 0; dj < 8; ++dj) {
        int d = dj * 8 + dcol;
        {
            float v0 = O[dj][0] * inv0, v1 = O[dj][1] * inv0;
            __half h0 = __float2half_rn(v0), h1 = __float2half_rn(v1);
            *(uint32_t*)&g_cxh[base0 + d] = packh2h(h0, h1);
            *(uint32_t*)&g_cxl[base0 + d] = packh2(v0 - __half2float(h0),
                                                   v1 - __half2float(h1));
        }
        {
            float v2 = O[dj][2] * inv1, v3 = O[dj][3] * inv1;
            __half h2 = __float2half_rn(v2), h3 = __float2half_rn(v3);
            *(uint32_t*)&g_cxh[base1 + d] = packh2h(h2, h3);
            *(uint32_t*)&g_cxl[base1 + d] = packh2(v2 - __half2float(h2),
                                                   v3 - __half2float(h3));
        }
    }
}

// ---------------------------------------------------------------------------
extern "C" void kernel_launch(void* const* d_in, const int* in_sizes, int n_in,
                              void* d_out, int out_size)
{
    const float* x  = (const float*)d_in[0];
    const float* Wq = (const float*)d_in[1];
    const float* Wk = (const float*)d_in[2];
    const float* Wv = (const float*)d_in[3];
    const float* Wo = (const float*)d_in[4];
    const float* bo = (const float*)d_in[5];
    float* out = (float*)d_out;

    cudaFuncSetAttribute(mma_gemm<0>, cudaFuncAttributeMaxDynamicSharedMemorySize, GSMEM);
    cudaFuncSetAttribute(mma_gemm<1>, cudaFuncAttributeMaxDynamicSharedMemorySize, GSMEM);
    cudaFuncSetAttribute(attn_mma_kernel, cudaFuncAttributeMaxDynamicSharedMemorySize, ATTN_SMEM);

    conv_all_kernel<<<12288, 256>>>(x, Wq, Wk, Wv, Wo);
    mma_gemm<0><<<dim3(128, 8, 3), 128, GSMEM>>>(nullptr, nullptr);
    attn_mma_kernel<<<dim3(32, HH, BB), 128, ATTN_SMEM>>>();
    mma_gemm<1><<<dim3(128, 8), 128, GSMEM>>>(bo, out);
}

// round 16
// speedup vs baseline: 2.4479x; 1.1871x over previous
#include <cuda_runtime.h>
#include <cuda_fp16.h>
#include <cstdint>

#define BB   4
#define HH   16
#define SS   2048
#define HD   64
#define DIN  1024
#define DOUT 1024

// ---------------------------------------------------------------------------
// Scratch (__device__ globals; no allocations allowed).  All-fp16 activations.
// ---------------------------------------------------------------------------
__device__ __half g_xh[BB * SS * DIN];       // x fp16
__device__ __half g_wth[4 * DIN * DOUT];     // W^T fp16 [n][k], 4 mats
__device__ __half g_qh[BB * HH * SS * HD];   // Q (pre-scaled) [B,H,S,HD]
__device__ __half g_kh[BB * HH * SS * HD];
__device__ __half g_vh[BB * HH * SS * HD];
__device__ __half g_cxh[BB * SS * DOUT];     // ctx fp16 [8192][1024]

// ---------------------------------------------------------------------------
// Helpers
// ---------------------------------------------------------------------------
__device__ __forceinline__ uint32_t smem_u32(const void* p) {
    uint32_t a;
    asm("{ .reg .u64 t; cvta.to.shared.u64 t, %1; cvt.u32.u64 %0, t; }" : "=r"(a) : "l"(p));
    return a;
}
__device__ __forceinline__ float ex2(float x) {
    float y;
    asm("ex2.approx.f32 %0, %1;" : "=f"(y) : "f"(x));
    return y;
}
__device__ __forceinline__ uint32_t packh2(float a, float b) {
    __half2 t = __floats2half2_rn(a, b);
    return *(uint32_t*)&t;
}
__device__ __forceinline__ void ldsm4(uint32_t& r0, uint32_t& r1, uint32_t& r2, uint32_t& r3,
                                      uint32_t addr) {
    asm volatile("ldmatrix.sync.aligned.m8n8.x4.shared.b16 {%0,%1,%2,%3}, [%4];"
                 : "=r"(r0), "=r"(r1), "=r"(r2), "=r"(r3) : "r"(addr));
}
__device__ __forceinline__ void ldsm4t(uint32_t& r0, uint32_t& r1, uint32_t& r2, uint32_t& r3,
                                       uint32_t addr) {
    asm volatile("ldmatrix.sync.aligned.m8n8.x4.trans.shared.b16 {%0,%1,%2,%3}, [%4];"
                 : "=r"(r0), "=r"(r1), "=r"(r2), "=r"(r3) : "r"(addr));
}
__device__ __forceinline__ void mma16816(float* c, const uint32_t* a, const uint32_t* b) {
    asm volatile(
        "mma.sync.aligned.m16n8k16.row.col.f32.f16.f16.f32 "
        "{%0,%1,%2,%3}, {%4,%5,%6,%7}, {%8,%9}, {%0,%1,%2,%3};"
        : "+f"(c[0]), "+f"(c[1]), "+f"(c[2]), "+f"(c[3])
        : "r"(a[0]), "r"(a[1]), "r"(a[2]), "r"(a[3]), "r"(b[0]), "r"(b[1]));
}
__device__ __forceinline__ void cp16(uint32_t dst, const void* src) {
    asm volatile("cp.async.cg.shared.global [%0], [%1], 16;" :: "r"(dst), "l"(src));
}
__device__ __forceinline__ void cp_commit() { asm volatile("cp.async.commit_group;" ::: "memory"); }
__device__ __forceinline__ void cp_wait1()  { asm volatile("cp.async.wait_group 1;" ::: "memory"); }
__device__ __forceinline__ void cp_wait0()  { asm volatile("cp.async.wait_group 0;" ::: "memory"); }

// ---------------------------------------------------------------------------
// Merged conversion: blocks [0, 8192) convert x -> fp16; [8192, 12288) W^T -> fp16.
// ---------------------------------------------------------------------------
__global__ __launch_bounds__(256) void conv_all_kernel(
    const float* __restrict__ x,
    const float* __restrict__ Wq, const float* __restrict__ Wk,
    const float* __restrict__ Wv, const float* __restrict__ Wo)
{
    __shared__ float t[32][33];
    if (blockIdx.x < 8192) {
        int i = (blockIdx.x * 256 + threadIdx.x) * 4;
        float4 v = *(const float4*)(x + i);
        *(uint2*)&g_xh[i] = make_uint2(packh2(v.x, v.y), packh2(v.z, v.w));
    } else {
        const int w = blockIdx.x - 8192;
        const int z = w >> 10;
        const int b2 = w & 1023;
        const int n0 = (b2 & 31) * 32;
        const int k0 = (b2 >> 5) * 32;
        const float* W = (z == 0) ? Wq : (z == 1) ? Wk : (z == 2) ? Wv : Wo;
        const int tx = threadIdx.x & 31, ty = threadIdx.x >> 5;   // 32 x 8
        #pragma unroll
        for (int i = 0; i < 4; ++i)
            t[ty + i * 8][tx] = W[(size_t)(k0 + ty + i * 8) * DOUT + n0 + tx];
        __syncthreads();
        __half* wh = g_wth + (size_t)z * DIN * DOUT;
        #pragma unroll
        for (int i = 0; i < 4; ++i) {
            int n = n0 + ty + i * 8, k = k0 + tx;
            wh[(size_t)n * DIN + k] = __float2half_rn(t[tx][ty + i * 8]);
        }
    }
}

// ---------------------------------------------------------------------------
// fp16 1-pass GEMM via mma.sync.  CTA 64x128, 128 threads (warp 32x64), KC=32,
// 2 stages, 3 CTAs/SM.
// MODE 0: A = x, B = W^T[z] -> Q/K/V fp16 (Q pre-scaled).
// MODE 1: A = ctx fp16, B = Wo^T, +bias -> d_out fp32.
// ---------------------------------------------------------------------------
#define KC     32
#define PITCH  80
#define ATILE  (64 * PITCH)              // 5120
#define BTILE  (128 * PITCH)             // 10240
#define STAGEB (ATILE + BTILE)           // 15360
#define GSMEM  (2 * STAGEB)              // 30720

template<int MODE>
__global__ __launch_bounds__(128, 3) void mma_gemm(const float* __restrict__ bias,
                                                   float* __restrict__ dout)
{
    extern __shared__ char smc[];
    const uint32_t smb = smem_u32(smc);

    const int tid  = threadIdx.x;
    const int lane = tid & 31;
    const int wid  = tid >> 5;
    const int wm   = (wid & 1) * 32;
    const int wn   = (wid >> 1) * 64;

    const int m0 = blockIdx.x * 64;
    const int n0 = blockIdx.y * 128;
    const int bz = (MODE == 0) ? blockIdx.z : 3;

    const __half* Ah = (MODE == 0) ? g_xh : g_cxh;
    const __half* Bh = g_wth + (size_t)bz * DIN * DOUT;

    const char* agh = (const char*)Ah + ((size_t)m0 * DIN) * 2;
    const char* bgh = (const char*)Bh + ((size_t)n0 * DIN) * 2;

    auto load = [&](int c, int st) {
        const uint32_t base = smb + st * STAGEB;
        const size_t cko = (size_t)c * KC * 2;
        #pragma unroll
        for (int i = 0; i < 2; ++i) {
            int s   = tid + i * 128;
            int r   = s >> 2;
            int seg = s & 3;
            cp16(base + r * PITCH + seg * 16,
                 agh + (size_t)r * (DIN * 2) + cko + seg * 16);
        }
        #pragma unroll
        for (int i = 0; i < 4; ++i) {
            int s   = tid + i * 128;
            int r   = s >> 2;
            int seg = s & 3;
            cp16(base + ATILE + r * PITCH + seg * 16,
                 bgh + (size_t)r * (DIN * 2) + cko + seg * 16);
        }
    };

    float C[2][8][4] = {};

    const uint32_t aRow = wm + (lane & 15);
    const uint32_t aCol = (lane >> 4) * 16;
    const uint32_t bRow = wn + ((lane >> 4) << 3) + (lane & 7);
    const uint32_t bCol = ((lane >> 3) & 1) * 16;

    load(0, 0);
    cp_commit();

    for (int c = 0; c < DIN / KC; ++c) {
        const int st = c & 1;
        if (c + 1 < DIN / KC) { load(c + 1, st ^ 1); cp_commit(); cp_wait1(); }
        else                  { cp_wait0(); }
        __syncthreads();

        const uint32_t sA = smb + st * STAGEB;
        const uint32_t sB = sA + ATILE;

        #pragma unroll
        for (int ks = 0; ks < 2; ++ks) {
            uint32_t ah[2][4], bh[8][2];
            #pragma unroll
            for (int i = 0; i < 2; ++i) {
                uint32_t ad = sA + (aRow + i * 16) * PITCH + ks * 32 + aCol;
                ldsm4(ah[i][0], ah[i][1], ah[i][2], ah[i][3], ad);
            }
            #pragma unroll
            for (int p = 0; p < 4; ++p) {
                uint32_t bd = sB + (bRow + p * 16) * PITCH + ks * 32 + bCol;
                ldsm4(bh[2*p][0], bh[2*p][1], bh[2*p+1][0], bh[2*p+1][1], bd);
            }
            #pragma unroll
            for (int i = 0; i < 2; ++i)
                #pragma unroll
                for (int j = 0; j < 8; ++j)
                    mma16816(C[i][j], ah[i], bh[j]);
        }
        __syncthreads();
    }

    // ---- epilogue ----
    const int rr = lane >> 2;
    const int cc = (lane & 3) * 2;
    const float scl = (MODE == 0 && bz == 0) ? 0.1803368801111244f : 1.0f; // (1/8)*log2(e)
    #pragma unroll
    for (int i = 0; i < 2; ++i) {
        #pragma unroll
        for (int j = 0; j < 8; ++j) {
            int m1 = m0 + wm + i * 16 + rr;
            int m2 = m1 + 8;
            int n  = n0 + wn + j * 8 + cc;
            if (MODE == 0) {
                __half* oh = (bz == 0) ? g_qh : (bz == 1) ? g_kh : g_vh;
                int head = n >> 6, hd = n & 63;
                #pragma unroll
                for (int half = 0; half < 2; ++half) {
                    int mm = half ? m2 : m1;
                    int b = mm >> 11, s = mm & 2047;
                    size_t idx = (((size_t)(b * HH + head) * SS + s) * HD) + hd;
                    *(uint32_t*)&oh[idx] = packh2(C[i][j][half * 2] * scl,
                                                  C[i][j][half * 2 + 1] * scl);
                }
            } else {
                float b0 = bias[n], b1 = bias[n + 1];
                *(float2*)&dout[(size_t)m1 * DOUT + n] = make_float2(C[i][j][0] + b0, C[i][j][1] + b1);
                *(float2*)&dout[(size_t)m2 * DOUT + n] = make_float2(C[i][j][2] + b0, C[i][j][3] + b1);
            }
        }
    }
}

// ---------------------------------------------------------------------------
// Causal flash attention (fp16, max-free softmax, ex2.approx).
// S = 1-pass (Q*K);  PV = 1-pass (P fp16 * V).  ctx stored fp16.
// CTA: 64 queries x (b,h), 128 threads.  KV tiles of 32, 3 CTAs/SM.
// ---------------------------------------------------------------------------
#define APITCH  144
#define QBYTES  (64 * APITCH)           // 9216
#define KVB     (32 * APITCH)           // 4608
#define OFF_ST  QBYTES
#define STG_B   (2 * KVB)               // 9216 (Kh, Vh)
#define ATTN_SMEM (OFF_ST + 2 * STG_B)  // 27648

__global__ __launch_bounds__(128, 3) void attn_mma_kernel()
{
    extern __shared__ char smc[];
    const uint32_t smb = smem_u32(smc);

    const int tid  = threadIdx.x;
    const int lane = tid & 31;
    const int wid  = tid >> 5;
    const int qt   = (int)(gridDim.x - 1) - (int)blockIdx.x;  // heavy tiles first
    const int h    = blockIdx.y, b = blockIdx.z;
    const int wq   = wid * 16;

    const size_t bh = ((size_t)(b * HH + h)) * SS;
    const char* gqh = (const char*)(g_qh + (bh + (size_t)qt * 64) * HD);
    const char* gkh = (const char*)(g_kh + bh * HD);
    const char* gvh = (const char*)(g_vh + bh * HD);

    #pragma unroll
    for (int i = 0; i < 4; ++i) {
        int s = tid + i * 128;
        int r = s >> 3, seg = s & 7;
        cp16(smb + r * APITCH + seg * 16, gqh + (size_t)r * 128 + seg * 16);
    }
    auto loadKV = [&](int jt, int st) {
        const uint32_t base = smb + OFF_ST + st * STG_B;
        const size_t g0 = (size_t)jt * 32 * 128;
        #pragma unroll
        for (int i = 0; i < 2; ++i) {
            int s = tid + i * 128;
            int r = s >> 3, seg = s & 7;
            uint32_t doff = r * APITCH + seg * 16;
            size_t   goff = g0 + (size_t)r * 128 + seg * 16;
            cp16(base + doff,       gkh + goff);
            cp16(base + KVB + doff, gvh + goff);
        }
    };
    loadKV(0, 0);
    cp_commit();

    uint32_t qh[4][4];
    float O[8][4] = {};
    float rs0 = 0.f, rs1 = 0.f;

    const uint32_t aoff = (wq + (lane & 15)) * APITCH + (lane >> 4) * 16;
    const uint32_t krow = (((lane >> 4) << 3) + (lane & 7)) * APITCH + ((lane >> 3) & 1) * 16;
    const uint32_t vrow = (lane & 15) * APITCH + (lane >> 4) * 16;

    const int jmax = 2 * qt + 1;
    for (int jt = 0; jt <= jmax; ++jt) {
        const int st = jt & 1;
        if (jt < jmax) { loadKV(jt + 1, st ^ 1); cp_commit(); cp_wait1(); }
        else           { cp_wait0(); }
        __syncthreads();

        if (jt == 0) {
            #pragma unroll
            for (int f = 0; f < 4; ++f)
                ldsm4(qh[f][0], qh[f][1], qh[f][2], qh[f][3], smb + aoff + f * 32);
        }

        const bool active = !(jt == jmax && wq < 32);
        if (active) {
            const uint32_t kb = smb + OFF_ST + st * STG_B;

            // ---- S = Q K^T (1-pass fp16) ----
            float s_[4][4] = {};
            #pragma unroll
            for (int f = 0; f < 4; ++f) {
                uint32_t kh[2][4];
                #pragma unroll
                for (int jp = 0; jp < 2; ++jp) {
                    uint32_t a = kb + krow + jp * 16 * APITCH + f * 32;
                    ldsm4(kh[jp][0], kh[jp][1], kh[jp][2], kh[jp][3], a);
                }
                #pragma unroll
                for (int jp = 0; jp < 2; ++jp) {
                    mma16816(s_[2*jp],     qh[f], kh[jp]);
                    mma16816(s_[2*jp + 1], qh[f], kh[jp] + 2);
                }
            }

            if (jt >= 2 * qt) {
                const int qrow  = qt * 64 + wq + (lane >> 2);
                const int kcol0 = jt * 32 + (lane & 3) * 2;
                #pragma unroll
                for (int j = 0; j < 4; ++j) {
                    int c0 = kcol0 + j * 8, c1 = c0 + 1;
                    if (c0 > qrow)     s_[j][0] = -1e30f;
                    if (c1 > qrow)     s_[j][1] = -1e30f;
                    if (c0 > qrow + 8) s_[j][2] = -1e30f;
                    if (c1 > qrow + 8) s_[j][3] = -1e30f;
                }
            }

            // ---- max-free softmax (MUFU.EX2) ----
            #pragma unroll
            for (int j = 0; j < 4; ++j) {
                s_[j][0] = ex2(s_[j][0]);
                s_[j][1] = ex2(s_[j][1]);
                s_[j][2] = ex2(s_[j][2]);
                s_[j][3] = ex2(s_[j][3]);
                rs0 += s_[j][0] + s_[j][1];
                rs1 += s_[j][2] + s_[j][3];
            }

            // ---- O += P V (1-pass, P rounded to fp16) ----
            const uint32_t vb = kb + KVB + vrow;
            #pragma unroll
            for (int f = 0; f < 2; ++f) {
                uint32_t ph[4];
                #pragma unroll
                for (int t = 0; t < 2; ++t) {
                    ph[2*t]   = packh2(s_[2*f + t][0], s_[2*f + t][1]);
                    ph[2*t+1] = packh2(s_[2*f + t][2], s_[2*f + t][3]);
                }
                const uint32_t va = vb + f * 16 * APITCH;
                uint32_t vh[4][4];
                #pragma unroll
                for (int dj = 0; dj < 4; ++dj)
                    ldsm4t(vh[dj][0], vh[dj][1], vh[dj][2], vh[dj][3], va + dj * 32);
                #pragma unroll
                for (int dj = 0; dj < 4; ++dj) {
                    mma16816(O[2*dj],     ph, vh[dj]);
                    mma16816(O[2*dj + 1], ph, vh[dj] + 2);
                }
            }
        }
        __syncthreads();
    }

    // ---- finalize ----
    rs0 += __shfl_xor_sync(0xffffffffu, rs0, 1);
    rs0 += __shfl_xor_sync(0xffffffffu, rs0, 2);
    rs1 += __shfl_xor_sync(0xffffffffu, rs1, 1);
    rs1 += __shfl_xor_sync(0xffffffffu, rs1, 2);
    const float inv0 = 1.0f / rs0, inv1 = 1.0f / rs1;

    const int r    = lane >> 2;
    const int dcol = (lane & 3) * 2;
    const int row0 = qt * 64 + wq + r;
    const size_t base0 = ((size_t)b * SS + row0) * DOUT + h * 64;
    const size_t base1 = base0 + (size_t)8 * DOUT;
    #pragma unroll
    for (int dj = 0; dj < 8; ++dj) {
        int d = dj * 8 + dcol;
        *(uint32_t*)&g_cxh[base0 + d] = packh2(O[dj][0] * inv0, O[dj][1] * inv0);
        *(uint32_t*)&g_cxh[base1 + d] = packh2(O[dj][2] * inv1, O[dj][3] * inv1);
    }
}

// ---------------------------------------------------------------------------
extern "C" void kernel_launch(void* const* d_in, const int* in_sizes, int n_in,
                              void* d_out, int out_size)
{
    const float* x  = (const float*)d_in[0];
    const float* Wq = (const float*)d_in[1];
    const float* Wk = (const float*)d_in[2];
    const float* Wv = (const float*)d_in[3];
    const float* Wo = (const float*)d_in[4];
    const float* bo = (const float*)d_in[5];
    float* out = (float*)d_out;

    cudaFuncSetAttribute(mma_gemm<0>, cudaFuncAttributeMaxDynamicSharedMemorySize, GSMEM);
    cudaFuncSetAttribute(mma_gemm<1>, cudaFuncAttributeMaxDynamicSharedMemorySize, GSMEM);
    cudaFuncSetAttribute(attn_mma_kernel, cudaFuncAttributeMaxDynamicSharedMemorySize, ATTN_SMEM);

    conv_all_kernel<<<12288, 256>>>(x, Wq, Wk, Wv, Wo);
    mma_gemm<0><<<dim3(128, 8, 3), 128, GSMEM>>>(nullptr, nullptr);
    attn_mma_kernel<<<dim3(32, HH, BB), 128, ATTN_SMEM>>>();
    mma_gemm<1><<<dim3(128, 8), 128, GSMEM>>>(bo, out);
}